// round 1
// baseline (speedup 1.0000x reference)
#include <cuda_runtime.h>
#include <cuda_bf16.h>
#include <math.h>

// ---------------------------------------------------------------------------
// RoPE-LoFTR encoder layer, FP32 baseline.
// Shapes (from setup_inputs): N=4, L=16384 (H=W=128), C=256, NHEAD=8, D=32.
// Pipeline:
//   q = x@Wq^T ; k = src@Wk^T ; v = src@Wv^T            (SGEMM x3)
//   q,k <- rope(elu(.)+1)                                (elementwise)
//   KV[n,h] = sum_s K[s]^T v[s] ; Ksum[n,h] = sum_s K[s] (chunked reduce, deterministic)
//   msg = (Q @ KV) / (Q.Ksum + eps)                      (v/L and *L cancel)
//   t1 = LN1(msg @ Wm^T)
//   h1 = relu([x, t1] @ W1^T)                            (K-split SGEMM, no concat buffer)
//   t2 = h1 @ W2^T
//   out = x + LN2(t2)
// ---------------------------------------------------------------------------

#define MAXM  65536          // N*L
#define CDIM  256
#define LSEQ  16384
#define WGRID 128
#define NHEAD 8
#define NCHUNK 32            // s-chunks for KV reduction

__device__ float g_q  [(size_t)MAXM * CDIM];
__device__ float g_k  [(size_t)MAXM * CDIM];
__device__ float g_v  [(size_t)MAXM * CDIM];
__device__ float g_msg[(size_t)MAXM * CDIM];
__device__ float g_t1 [(size_t)MAXM * CDIM];
__device__ float g_h1 [(size_t)MAXM * 2 * CDIM];
__device__ float g_kvp[(size_t)NCHUNK * 32 * 32 * 32];  // chunk x nh x d x e
__device__ float g_ksp[(size_t)NCHUNK * 32 * 32];       // chunk x nh x d
__device__ float g_kv [(size_t)32 * 32 * 32];           // nh x d x e
__device__ float g_ksum[(size_t)32 * 32];               // nh x d

// ---------------------------------------------------------------------------
// SGEMM:  Cout[m,n] = sum_k Asrc[m,k] * B[n,k]   (A row-major, B = weight N x K)
// A source switches from A(lda) to A2(lda2) at k = Ksplit (for the concat GEMM).
// BM=BN=128, BK=8, 256 threads, 8x8 per thread.
// ---------------------------------------------------------------------------
template <bool RELU>
__global__ __launch_bounds__(256) void sgemm_nt(
    const float* __restrict__ A, int lda,
    const float* __restrict__ A2, int lda2, int Ksplit,
    const float* __restrict__ B,
    float* __restrict__ Cout,
    int M, int N, int K)
{
    constexpr int BM = 128, BN = 128, BK = 8;
    __shared__ float As[BK][BM];
    __shared__ float Bs[BK][BN];

    const int bm = blockIdx.y * BM;
    const int bn = blockIdx.x * BN;
    const int t  = threadIdx.x;
    const int tx = t & 15;        // 0..15 -> 8 cols each
    const int ty = t >> 4;        // 0..15 -> 8 rows each
    const int lrow = t >> 1;      // 0..127
    const int lk4  = (t & 1) << 2;

    float acc[8][8];
#pragma unroll
    for (int i = 0; i < 8; i++)
#pragma unroll
        for (int j = 0; j < 8; j++) acc[i][j] = 0.f;

    for (int k0 = 0; k0 < K; k0 += BK) {
        const float* Ap; int kk0; int ld;
        if (k0 < Ksplit) { Ap = A;  kk0 = k0;          ld = lda;  }
        else             { Ap = A2; kk0 = k0 - Ksplit; ld = lda2; }

        float4 av = *(const float4*)(Ap + (size_t)(bm + lrow) * ld + kk0 + lk4);
        float4 bv = *(const float4*)(B  + (size_t)(bn + lrow) * K  + k0  + lk4);
        As[lk4 + 0][lrow] = av.x; As[lk4 + 1][lrow] = av.y;
        As[lk4 + 2][lrow] = av.z; As[lk4 + 3][lrow] = av.w;
        Bs[lk4 + 0][lrow] = bv.x; Bs[lk4 + 1][lrow] = bv.y;
        Bs[lk4 + 2][lrow] = bv.z; Bs[lk4 + 3][lrow] = bv.w;
        __syncthreads();

#pragma unroll
        for (int kk = 0; kk < BK; kk++) {
            float ar[8], br[8];
            *(float4*)&ar[0] = *(const float4*)&As[kk][ty * 8];
            *(float4*)&ar[4] = *(const float4*)&As[kk][ty * 8 + 4];
            *(float4*)&br[0] = *(const float4*)&Bs[kk][tx * 8];
            *(float4*)&br[4] = *(const float4*)&Bs[kk][tx * 8 + 4];
#pragma unroll
            for (int i = 0; i < 8; i++)
#pragma unroll
                for (int j = 0; j < 8; j++)
                    acc[i][j] += ar[i] * br[j];
        }
        __syncthreads();
    }

#pragma unroll
    for (int i = 0; i < 8; i++) {
        size_t rbase = (size_t)(bm + ty * 8 + i) * N + bn + tx * 8;
#pragma unroll
        for (int j0 = 0; j0 < 8; j0 += 4) {
            float4 o;
            o.x = acc[i][j0 + 0]; o.y = acc[i][j0 + 1];
            o.z = acc[i][j0 + 2]; o.w = acc[i][j0 + 3];
            if (RELU) {
                o.x = fmaxf(o.x, 0.f); o.y = fmaxf(o.y, 0.f);
                o.z = fmaxf(o.z, 0.f); o.w = fmaxf(o.w, 0.f);
            }
            *(float4*)(Cout + rbase + j0) = o;
        }
    }
}

// ---------------------------------------------------------------------------
// elu(.)+1 followed by RoPE, in place, applied to q (blockIdx.y=0) and k (=1).
// One thread per (token, dim-pair). Layout: [M, C], C = NHEAD*32, pair index
// rem in [0,128): head = rem/16, t = rem%16. For pair t: freq q = t>>1,
// position = (i+1) if t even else (j+1), where l = i*WGRID + j.
// ---------------------------------------------------------------------------
__global__ __launch_bounds__(256) void rope_prep(float* __restrict__ q,
                                                 float* __restrict__ k,
                                                 int M)
{
    int idx = blockIdx.x * 256 + threadIdx.x;
    int total = M * 128;
    if (idx >= total) return;
    float* arr = blockIdx.y ? k : q;

    int m   = idx >> 7;
    int rem = idx & 127;
    int tt  = rem & 15;
    int l = m % LSEQ;
    int i = l / WGRID, j = l % WGRID;
    int qf = tt >> 1;
    float pos = (tt & 1) ? (float)(j + 1) : (float)(i + 1);
    float dv  = expf(-(float)qf * 1.1512925465f);  // ln(10000)/8
    float ang = pos * dv;
    float s, c;
    sincosf(ang, &s, &c);

    size_t off = (size_t)m * CDIM + rem * 2;
    float2 v = *(float2*)(arr + off);
    float x0 = v.x > 0.f ? v.x + 1.f : expf(v.x);
    float x1 = v.y > 0.f ? v.y + 1.f : expf(v.y);
    float2 o;
    o.x = x0 * c - x1 * s;
    o.y = x1 * c + x0 * s;
    *(float2*)(arr + off) = o;
}

// ---------------------------------------------------------------------------
// Chunked KV / Ksum partial reduction. grid = (NCHUNK, NH), 256 threads.
// Thread t: d = t&31, e-group eg = t>>5 (4 e's each). Deterministic (no atomics).
// ---------------------------------------------------------------------------
__global__ __launch_bounds__(256) void kv_reduce(
    const float* __restrict__ Kr, const float* __restrict__ V,
    float* __restrict__ kvp, float* __restrict__ ksp, int NH)
{
    int chunk = blockIdx.x;
    int nh    = blockIdx.y;
    int n = nh >> 3, h = nh & 7;
    int t = threadIdx.x;
    int d = t & 31, eg = t >> 5;
    const int rows = LSEQ / NCHUNK;   // 512
    int s0 = chunk * rows;

    __shared__ float Ks[8][32];
    __shared__ float Vs[8][32];

    float a0 = 0.f, a1 = 0.f, a2 = 0.f, a3 = 0.f, ks = 0.f;
    int ls = t >> 5, ld = t & 31;

    for (int s = 0; s < rows; s += 8) {
        size_t off = (size_t)(n * LSEQ + s0 + s + ls) * CDIM + h * 32 + ld;
        Ks[ls][ld] = Kr[off];
        Vs[ls][ld] = V[off];
        __syncthreads();
#pragma unroll
        for (int ss = 0; ss < 8; ss++) {
            float kd = Ks[ss][d];
            if (eg == 0) ks += kd;
            const float* vr = &Vs[ss][eg * 4];
            a0 += kd * vr[0];
            a1 += kd * vr[1];
            a2 += kd * vr[2];
            a3 += kd * vr[3];
        }
        __syncthreads();
    }

    size_t pbase = ((size_t)(chunk * NH + nh) * 32 + d) * 32 + eg * 4;
    kvp[pbase + 0] = a0; kvp[pbase + 1] = a1;
    kvp[pbase + 2] = a2; kvp[pbase + 3] = a3;
    if (eg == 0) ksp[(size_t)(chunk * NH + nh) * 32 + d] = ks;
}

__global__ void kv_finalize(const float* __restrict__ kvp,
                            const float* __restrict__ ksp,
                            float* __restrict__ kv, float* __restrict__ ksum,
                            int NH)
{
    int i = blockIdx.x * blockDim.x + threadIdx.x;
    int tot_kv = NH * 1024;
    int tot_ks = NH * 32;
    if (i < tot_kv) {
        float s = 0.f;
        for (int c = 0; c < NCHUNK; c++) s += kvp[(size_t)c * tot_kv + i];
        kv[i] = s;
    } else if (i < tot_kv + tot_ks) {
        int j = i - tot_kv;
        float s = 0.f;
        for (int c = 0; c < NCHUNK; c++) s += ksp[(size_t)c * tot_ks + j];
        ksum[j] = s;
    }
}

// ---------------------------------------------------------------------------
// Per-token attention output: one warp per (token, head).
// Z = 1/(Q . Ksum + eps); out[e] = Z * sum_d Q[d] * KV[d][e].
// (v/L normalization and *L restore cancel exactly.)
// ---------------------------------------------------------------------------
__global__ __launch_bounds__(256) void attn_out(
    const float* __restrict__ Q, const float* __restrict__ KV,
    const float* __restrict__ Ksum, float* __restrict__ out)
{
    int m = blockIdx.x;
    int w = threadIdx.x >> 5;
    int lane = threadIdx.x & 31;
    int n = m / LSEQ;
    int nh = n * NHEAD + w;

    float qv = Q[(size_t)m * CDIM + w * 32 + lane];
    float z = qv * Ksum[nh * 32 + lane];
#pragma unroll
    for (int o = 16; o; o >>= 1) z += __shfl_xor_sync(0xffffffffu, z, o);
    float Z = 1.f / (z + 1e-6f);

    const float* kvh = KV + (size_t)nh * 1024;
    float acc = 0.f;
#pragma unroll
    for (int d = 0; d < 32; d++)
        acc += __shfl_sync(0xffffffffu, qv, d) * kvh[d * 32 + lane];

    out[(size_t)m * CDIM + w * 32 + lane] = acc * Z;
}

// ---------------------------------------------------------------------------
// LayerNorm over C=256 (biased variance), optional residual add.
// One block per row, 256 threads.
// ---------------------------------------------------------------------------
__global__ __launch_bounds__(256) void ln_kernel(
    const float* __restrict__ in, const float* __restrict__ g,
    const float* __restrict__ b, const float* __restrict__ resid,
    float* __restrict__ out)
{
    int row = blockIdx.x, t = threadIdx.x;
    int lane = t & 31, w = t >> 5;
    size_t base = (size_t)row * CDIM + t;
    float x = in[base];

    __shared__ float red[8];
    __shared__ float stat;

    float s = x;
#pragma unroll
    for (int o = 16; o; o >>= 1) s += __shfl_xor_sync(0xffffffffu, s, o);
    if (lane == 0) red[w] = s;
    __syncthreads();
    if (t == 0) {
        float m = 0.f;
#pragma unroll
        for (int i = 0; i < 8; i++) m += red[i];
        stat = m * (1.0f / 256.0f);
    }
    __syncthreads();
    float mean = stat;
    float d = x - mean;
    __syncthreads();

    float vs = d * d;
#pragma unroll
    for (int o = 16; o; o >>= 1) vs += __shfl_xor_sync(0xffffffffu, vs, o);
    if (lane == 0) red[w] = vs;
    __syncthreads();
    if (t == 0) {
        float vv = 0.f;
#pragma unroll
        for (int i = 0; i < 8; i++) vv += red[i];
        stat = rsqrtf(vv * (1.0f / 256.0f) + 1e-5f);
    }
    __syncthreads();

    float r = d * stat * g[t] + b[t];
    if (resid) r += resid[base];
    out[base] = r;
}

// ---------------------------------------------------------------------------
extern "C" void kernel_launch(void* const* d_in, const int* in_sizes, int n_in,
                              void* d_out, int out_size)
{
    const float* x    = (const float*)d_in[0];
    const float* src  = (const float*)d_in[1];
    const float* Wq   = (const float*)d_in[2];
    const float* Wk   = (const float*)d_in[3];
    const float* Wv   = (const float*)d_in[4];
    const float* Wm   = (const float*)d_in[5];
    const float* W1   = (const float*)d_in[6];
    const float* W2   = (const float*)d_in[7];
    const float* ln1g = (const float*)d_in[8];
    const float* ln1b = (const float*)d_in[9];
    const float* ln2g = (const float*)d_in[10];
    const float* ln2b = (const float*)d_in[11];

    const int C = CDIM;
    const int M = in_sizes[0] / C;       // N*L = 65536
    const int Nb = M / LSEQ;             // 4
    const int NH = Nb * NHEAD;           // 32

    float *q, *k, *v, *msg, *t1, *h1, *kvp, *ksp, *kv, *ksum;
    cudaGetSymbolAddress((void**)&q,    g_q);
    cudaGetSymbolAddress((void**)&k,    g_k);
    cudaGetSymbolAddress((void**)&v,    g_v);
    cudaGetSymbolAddress((void**)&msg,  g_msg);
    cudaGetSymbolAddress((void**)&t1,   g_t1);
    cudaGetSymbolAddress((void**)&h1,   g_h1);
    cudaGetSymbolAddress((void**)&kvp,  g_kvp);
    cudaGetSymbolAddress((void**)&ksp,  g_ksp);
    cudaGetSymbolAddress((void**)&kv,   g_kv);
    cudaGetSymbolAddress((void**)&ksum, g_ksum);

    float* outp = (float*)d_out;

    dim3 gq(C / 128, M / 128);
    // q/k/v projections
    sgemm_nt<false><<<gq, 256>>>(x,   C, x,   C, C, Wq, q, M, C, C);
    sgemm_nt<false><<<gq, 256>>>(src, C, src, C, C, Wk, k, M, C, C);
    sgemm_nt<false><<<gq, 256>>>(src, C, src, C, C, Wv, v, M, C, C);

    // elu+1 and RoPE on q and k
    {
        int total = M * 128;
        dim3 gr((total + 255) / 256, 2);
        rope_prep<<<gr, 256>>>(q, k, M);
    }

    // KV / Ksum
    kv_reduce<<<dim3(NCHUNK, NH), 256>>>(k, v, kvp, ksp, NH);
    {
        int tot = NH * 1024 + NH * 32;
        kv_finalize<<<(tot + 255) / 256, 256>>>(kvp, ksp, kv, ksum, NH);
    }

    // per-token attention output -> msg
    attn_out<<<M, 256>>>(q, kv, ksum, msg);

    // t1 = LN1(msg @ Wm^T)
    sgemm_nt<false><<<gq, 256>>>(msg, C, msg, C, C, Wm, t1, M, C, C);
    ln_kernel<<<M, 256>>>(t1, ln1g, ln1b, nullptr, t1);

    // h1 = relu([x, t1] @ W1^T)   (K=512, N=512, split at 256)
    sgemm_nt<true><<<dim3(2 * C / 128, M / 128), 256>>>(
        x, C, t1, C, C, W1, h1, M, 2 * C, 2 * C);

    // t2 = h1 @ W2^T  (reuse q buffer)
    sgemm_nt<false><<<gq, 256>>>(h1, 2 * C, h1, 2 * C, 2 * C, W2, q, M, C, 2 * C);

    // out = x + LN2(t2)
    ln_kernel<<<M, 256>>>(q, ln2g, ln2b, x, outp);
}

// round 3
// speedup vs baseline: 1.9777x; 1.9777x over previous
#include <cuda_runtime.h>
#include <cuda_bf16.h>
#include <cstdint>
#include <math.h>

// ---------------------------------------------------------------------------
// RoPE-LoFTR encoder layer. GEMMs via mma.sync bf16 (2-term split, fp32 acc).
// N=4, L=16384 (128x128), C=256, NHEAD=8, D=32.
// ---------------------------------------------------------------------------

#define MAXM   65536
#define CDIM   256
#define LSEQ   16384
#define WGRID  128
#define NHEADS 8
#define NCHUNK 32

typedef __nv_bfloat16 bf16;

// fp32 buffers
__device__ float g_q  [(size_t)MAXM * CDIM];
__device__ float g_k  [(size_t)MAXM * CDIM];
__device__ float g_v  [(size_t)MAXM * CDIM];
__device__ float g_t1f[(size_t)MAXM * CDIM];
__device__ float g_kvp[(size_t)NCHUNK * 32 * 32 * 32];
__device__ float g_ksp[(size_t)NCHUNK * 32 * 32];
__device__ float g_kv [(size_t)32 * 32 * 32];
__device__ float g_ksum[(size_t)32 * 32];

// bf16 hi/lo buffers
__device__ bf16 g_xhi[(size_t)MAXM * CDIM];
__device__ bf16 g_xlo[(size_t)MAXM * CDIM];
__device__ bf16 g_shi[(size_t)MAXM * CDIM];
__device__ bf16 g_slo[(size_t)MAXM * CDIM];
__device__ bf16 g_mhi[(size_t)MAXM * CDIM];
__device__ bf16 g_mlo[(size_t)MAXM * CDIM];
__device__ bf16 g_t1hi[(size_t)MAXM * CDIM];
__device__ bf16 g_t1lo[(size_t)MAXM * CDIM];
__device__ bf16 g_h1hi[(size_t)MAXM * 2 * CDIM];
__device__ bf16 g_h1lo[(size_t)MAXM * 2 * CDIM];
// weight hi/lo
__device__ bf16 g_wqhi[CDIM * CDIM], g_wqlo[CDIM * CDIM];
__device__ bf16 g_wkhi[CDIM * CDIM], g_wklo[CDIM * CDIM];
__device__ bf16 g_wvhi[CDIM * CDIM], g_wvlo[CDIM * CDIM];
__device__ bf16 g_wmhi[CDIM * CDIM], g_wmlo[CDIM * CDIM];
__device__ bf16 g_w1hi[2 * CDIM * 2 * CDIM], g_w1lo[2 * CDIM * 2 * CDIM];
__device__ bf16 g_w2hi[CDIM * 2 * CDIM], g_w2lo[CDIM * 2 * CDIM];

// ---------------------------------------------------------------------------
#define CP_ASYNC16(dst, src) \
    asm volatile("cp.async.cg.shared.global [%0], [%1], 16;" \
                 :: "r"(dst), "l"(src) : "memory")
#define CP_COMMIT() asm volatile("cp.async.commit_group;" ::: "memory")
#define CP_WAIT(n)  asm volatile("cp.async.wait_group %0;" :: "n"(n) : "memory")

__device__ __forceinline__ uint32_t smem_u32(const void* p) {
    uint32_t a;
    asm("{ .reg .u64 t; cvta.to.shared.u64 t, %1; cvt.u32.u64 %0, t; }"
        : "=r"(a) : "l"(p));
    return a;
}

__device__ __forceinline__ void mma16816(float* c, const uint32_t* a,
                                         const uint32_t* b) {
    asm volatile(
        "mma.sync.aligned.m16n8k16.row.col.f32.bf16.bf16.f32 "
        "{%0,%1,%2,%3}, {%4,%5,%6,%7}, {%8,%9}, {%0,%1,%2,%3};"
        : "+f"(c[0]), "+f"(c[1]), "+f"(c[2]), "+f"(c[3])
        : "r"(a[0]), "r"(a[1]), "r"(a[2]), "r"(a[3]), "r"(b[0]), "r"(b[1]));
}

// smem tile: 128 rows x 32 bf16 (64B/row); 16B chunk swizzle: ch ^= (row>>1)&3
__device__ __forceinline__ uint32_t tile_off(int row, int ch) {
    return (uint32_t)(row * 64 + ((ch ^ ((row >> 1) & 3)) << 4));
}

__device__ __forceinline__ uint32_t pack_bf16x2(float f0, float f1) {
    bf16 h0 = __float2bfloat16(f0);
    bf16 h1 = __float2bfloat16(f1);
    return (uint32_t)__bfloat16_as_ushort(h1) << 16 |
           (uint32_t)__bfloat16_as_ushort(h0);
}

// ---------------------------------------------------------------------------
// GEMM: C[M,N] = A[M,K] @ B[N,K]^T, A/B as bf16 hi/lo pairs; effective K=3K:
// seg0 Ahi*Bhi, seg1 Alo*Bhi, seg2 Ahi*Blo. A switches to A2 at k=Ksplit.
// Tile 128x128, BK=32, 256 threads (8 warps, 4m x 2n).
// OMODE 0: fp32 out. OMODE 1: bf16 hi/lo out (after optional RELU).
// ---------------------------------------------------------------------------
template <bool RELU, int OMODE>
__global__ __launch_bounds__(256) void gemm_mma(
    const bf16* __restrict__ Ahi, const bf16* __restrict__ Alo, int lda,
    const bf16* __restrict__ A2hi, const bf16* __restrict__ A2lo, int lda2,
    int Ksplit,
    const bf16* __restrict__ Bhi, const bf16* __restrict__ Blo,
    float* __restrict__ Cf, bf16* __restrict__ Chi, bf16* __restrict__ Clo,
    int M, int N, int K)
{
    __shared__ char smem[2][16384];   // per buf: A 8KB + B 8KB

    const int tid  = threadIdx.x;
    const int lane = tid & 31;
    const int wid  = tid >> 5;
    const int g    = lane >> 2;       // 0..7
    const int tig  = lane & 3;        // 0..3
    const int wm   = wid & 3;         // m-tile of 32 rows
    const int wn   = wid >> 2;        // n-tile of 64 cols
    const int bm   = blockIdx.y * 128;
    const int bn   = blockIdx.x * 128;
    const int kseg = K / 32;
    const int nkc  = 3 * kseg;

    float acc[2][8][4];
#pragma unroll
    for (int i = 0; i < 2; i++)
#pragma unroll
        for (int j = 0; j < 8; j++)
#pragma unroll
            for (int e = 0; e < 4; e++) acc[i][j][e] = 0.f;

    // per-thread store slots: 2 for A, 2 for B
    const int slot0 = tid, slot1 = tid + 256;

    auto issue = [&](int kc, int buf) {
        const int seg = kc / kseg;
        const int kin = (kc % kseg) * 32;
        const bf16* Asrc; int ald, koff;
        if (kin < Ksplit) { Asrc = (seg == 1) ? Alo : Ahi;  ald = lda;  koff = kin; }
        else              { Asrc = (seg == 1) ? A2lo : A2hi; ald = lda2; koff = kin - Ksplit; }
        const bf16* Bsrc = (seg == 2) ? Blo : Bhi;

        uint32_t sA = smem_u32(smem[buf]);
        uint32_t sB = sA + 8192;
        {
            int row = slot0 >> 2, ch = slot0 & 3;
            CP_ASYNC16(sA + tile_off(row, ch),
                       Asrc + (size_t)(bm + row) * ald + koff + ch * 8);
        }
        {
            int row = slot1 >> 2, ch = slot1 & 3;
            CP_ASYNC16(sA + tile_off(row, ch),
                       Asrc + (size_t)(bm + row) * ald + koff + ch * 8);
        }
        {
            int row = slot0 >> 2, ch = slot0 & 3;
            CP_ASYNC16(sB + tile_off(row, ch),
                       Bsrc + (size_t)(bn + row) * K + kin + ch * 8);
        }
        {
            int row = slot1 >> 2, ch = slot1 & 3;
            CP_ASYNC16(sB + tile_off(row, ch),
                       Bsrc + (size_t)(bn + row) * K + kin + ch * 8);
        }
        CP_COMMIT();
    };

    issue(0, 0);

    for (int kc = 0; kc < nkc; kc++) {
        const int buf = kc & 1;
        if (kc + 1 < nkc) { issue(kc + 1, buf ^ 1); CP_WAIT(1); }
        else              { CP_WAIT(0); }
        __syncthreads();

        const char* sA = smem[buf];
        const char* sB = smem[buf] + 8192;

#pragma unroll
        for (int s = 0; s < 2; s++) {           // two k16 steps
            uint32_t af[2][4];
#pragma unroll
            for (int mi = 0; mi < 2; mi++) {
                int r0 = wm * 32 + mi * 16 + g;
                int r1 = r0 + 8;
                af[mi][0] = *(const uint32_t*)(sA + tile_off(r0, 2 * s)     + tig * 4);
                af[mi][1] = *(const uint32_t*)(sA + tile_off(r1, 2 * s)     + tig * 4);
                af[mi][2] = *(const uint32_t*)(sA + tile_off(r0, 2 * s + 1) + tig * 4);
                af[mi][3] = *(const uint32_t*)(sA + tile_off(r1, 2 * s + 1) + tig * 4);
            }
            uint32_t bfr[8][2];
#pragma unroll
            for (int nj = 0; nj < 8; nj++) {
                int nr = wn * 64 + nj * 8 + g;
                bfr[nj][0] = *(const uint32_t*)(sB + tile_off(nr, 2 * s)     + tig * 4);
                bfr[nj][1] = *(const uint32_t*)(sB + tile_off(nr, 2 * s + 1) + tig * 4);
            }
#pragma unroll
            for (int mi = 0; mi < 2; mi++)
#pragma unroll
                for (int nj = 0; nj < 8; nj++)
                    mma16816(acc[mi][nj], af[mi], bfr[nj]);
        }
        __syncthreads();
    }

    // epilogue
#pragma unroll
    for (int mi = 0; mi < 2; mi++) {
        int row = bm + wm * 32 + mi * 16 + g;
#pragma unroll
        for (int nj = 0; nj < 8; nj++) {
            int col = bn + wn * 64 + nj * 8 + 2 * tig;
            float c0 = acc[mi][nj][0], c1 = acc[mi][nj][1];
            float c2 = acc[mi][nj][2], c3 = acc[mi][nj][3];
            if (RELU) {
                c0 = fmaxf(c0, 0.f); c1 = fmaxf(c1, 0.f);
                c2 = fmaxf(c2, 0.f); c3 = fmaxf(c3, 0.f);
            }
            if (OMODE == 0) {
                float2 o0 = make_float2(c0, c1);
                float2 o1 = make_float2(c2, c3);
                *(float2*)(Cf + (size_t)row * N + col)       = o0;
                *(float2*)(Cf + (size_t)(row + 8) * N + col) = o1;
            } else {
                uint32_t h0 = pack_bf16x2(c0, c1);
                uint32_t h1 = pack_bf16x2(c2, c3);
                bf16 hh;
                float r0l0 = c0 - __bfloat162float(__float2bfloat16(c0));
                float r0l1 = c1 - __bfloat162float(__float2bfloat16(c1));
                float r1l0 = c2 - __bfloat162float(__float2bfloat16(c2));
                float r1l1 = c3 - __bfloat162float(__float2bfloat16(c3));
                (void)hh;
                uint32_t l0 = pack_bf16x2(r0l0, r0l1);
                uint32_t l1 = pack_bf16x2(r1l0, r1l1);
                *(uint32_t*)(Chi + (size_t)row * N + col)       = h0;
                *(uint32_t*)(Chi + (size_t)(row + 8) * N + col) = h1;
                *(uint32_t*)(Clo + (size_t)row * N + col)       = l0;
                *(uint32_t*)(Clo + (size_t)(row + 8) * N + col) = l1;
            }
        }
    }
}

// ---------------------------------------------------------------------------
// fp32 -> bf16 hi/lo split (vectorized by 4)
// ---------------------------------------------------------------------------
__global__ __launch_bounds__(256) void split_kernel(const float* __restrict__ in,
                                                    bf16* __restrict__ hi,
                                                    bf16* __restrict__ lo, int n4)
{
    int i = blockIdx.x * 256 + threadIdx.x;
    if (i >= n4) return;
    float4 f = ((const float4*)in)[i];
    float fs[4] = {f.x, f.y, f.z, f.w};
    uint32_t hw[2], lw[2];
#pragma unroll
    for (int j = 0; j < 2; j++) {
        float a = fs[2 * j], b = fs[2 * j + 1];
        bf16 h0 = __float2bfloat16(a);
        bf16 h1 = __float2bfloat16(b);
        hw[j] = (uint32_t)__bfloat16_as_ushort(h1) << 16 |
                (uint32_t)__bfloat16_as_ushort(h0);
        lw[j] = pack_bf16x2(a - __bfloat162float(h0), b - __bfloat162float(h1));
    }
    ((uint2*)hi)[i] = make_uint2(hw[0], hw[1]);
    ((uint2*)lo)[i] = make_uint2(lw[0], lw[1]);
}

// ---------------------------------------------------------------------------
// elu+1 then RoPE in place on q and k (fp32)
// ---------------------------------------------------------------------------
__global__ __launch_bounds__(256) void rope_prep(float* __restrict__ q,
                                                 float* __restrict__ k, int M)
{
    int idx = blockIdx.x * 256 + threadIdx.x;
    if (idx >= M * 128) return;
    float* arr = blockIdx.y ? k : q;
    int m = idx >> 7, rem = idx & 127, tt = rem & 15;
    int l = m % LSEQ, i = l / WGRID, j = l % WGRID;
    int qf = tt >> 1;
    float pos = (tt & 1) ? (float)(j + 1) : (float)(i + 1);
    float ang = pos * expf(-(float)qf * 1.1512925465f);
    float s, c;
    sincosf(ang, &s, &c);
    size_t off = (size_t)m * CDIM + rem * 2;
    float2 v = *(float2*)(arr + off);
    float x0 = v.x > 0.f ? v.x + 1.f : expf(v.x);
    float x1 = v.y > 0.f ? v.y + 1.f : expf(v.y);
    float2 o;
    o.x = x0 * c - x1 * s;
    o.y = x1 * c + x0 * s;
    *(float2*)(arr + off) = o;
}

// ---------------------------------------------------------------------------
// KV / Ksum chunked reduction (deterministic), then finalize
// ---------------------------------------------------------------------------
__global__ __launch_bounds__(256) void kv_reduce(
    const float* __restrict__ Kr, const float* __restrict__ V,
    float* __restrict__ kvp, float* __restrict__ ksp, int NH)
{
    int chunk = blockIdx.x, nh = blockIdx.y;
    int n = nh >> 3, h = nh & 7;
    int t = threadIdx.x, d = t & 31, eg = t >> 5;
    const int rows = LSEQ / NCHUNK;
    int s0 = chunk * rows;
    __shared__ float Ks[8][32], Vs[8][32];
    float a0 = 0.f, a1 = 0.f, a2 = 0.f, a3 = 0.f, ks = 0.f;
    int ls = t >> 5, ld = t & 31;
    for (int s = 0; s < rows; s += 8) {
        size_t off = (size_t)(n * LSEQ + s0 + s + ls) * CDIM + h * 32 + ld;
        Ks[ls][ld] = Kr[off];
        Vs[ls][ld] = V[off];
        __syncthreads();
#pragma unroll
        for (int ss = 0; ss < 8; ss++) {
            float kd = Ks[ss][d];
            if (eg == 0) ks += kd;
            const float* vr = &Vs[ss][eg * 4];
            a0 += kd * vr[0]; a1 += kd * vr[1];
            a2 += kd * vr[2]; a3 += kd * vr[3];
        }
        __syncthreads();
    }
    size_t pbase = ((size_t)(chunk * NH + nh) * 32 + d) * 32 + eg * 4;
    kvp[pbase + 0] = a0; kvp[pbase + 1] = a1;
    kvp[pbase + 2] = a2; kvp[pbase + 3] = a3;
    if (eg == 0) ksp[(size_t)(chunk * NH + nh) * 32 + d] = ks;
}

__global__ void kv_finalize(const float* __restrict__ kvp, const float* __restrict__ ksp,
                            float* __restrict__ kv, float* __restrict__ ksum, int NH)
{
    int i = blockIdx.x * blockDim.x + threadIdx.x;
    int tot_kv = NH * 1024, tot_ks = NH * 32;
    if (i < tot_kv) {
        float s = 0.f;
        for (int c = 0; c < NCHUNK; c++) s += kvp[(size_t)c * tot_kv + i];
        kv[i] = s;
    } else if (i < tot_kv + tot_ks) {
        int j = i - tot_kv;
        float s = 0.f;
        for (int c = 0; c < NCHUNK; c++) s += ksp[(size_t)c * tot_ks + j];
        ksum[j] = s;
    }
}

// ---------------------------------------------------------------------------
// attention output per (token, head); writes msg as bf16 hi/lo
// ---------------------------------------------------------------------------
__global__ __launch_bounds__(256) void attn_out(
    const float* __restrict__ Q, const float* __restrict__ KV,
    const float* __restrict__ Ksum, bf16* __restrict__ mhi, bf16* __restrict__ mlo)
{
    int m = blockIdx.x, w = threadIdx.x >> 5, lane = threadIdx.x & 31;
    int n = m / LSEQ, nh = n * NHEADS + w;
    float qv = Q[(size_t)m * CDIM + w * 32 + lane];
    float z = qv * Ksum[nh * 32 + lane];
#pragma unroll
    for (int o = 16; o; o >>= 1) z += __shfl_xor_sync(0xffffffffu, z, o);
    float Z = 1.f / (z + 1e-6f);
    const float* kvh = KV + (size_t)nh * 1024;
    float acc = 0.f;
#pragma unroll
    for (int d = 0; d < 32; d++)
        acc += __shfl_sync(0xffffffffu, qv, d) * kvh[d * 32 + lane];
    float r = acc * Z;
    bf16 h = __float2bfloat16(r);
    bf16 l = __float2bfloat16(r - __bfloat162float(h));
    size_t off = (size_t)m * CDIM + w * 32 + lane;
    mhi[off] = h;
    mlo[off] = l;
}

// ---------------------------------------------------------------------------
// LayerNorm over C=256. BF16OUT: write hi/lo. Else fp32 (+optional residual).
// ---------------------------------------------------------------------------
template <bool BF16OUT>
__global__ __launch_bounds__(256) void ln_kernel(
    const float* __restrict__ in, const float* __restrict__ g,
    const float* __restrict__ b, const float* __restrict__ resid,
    float* __restrict__ outf, bf16* __restrict__ ohi, bf16* __restrict__ olo)
{
    int row = blockIdx.x, t = threadIdx.x;
    int lane = t & 31, w = t >> 5;
    size_t base = (size_t)row * CDIM + t;
    float x = in[base];
    __shared__ float red[8];
    __shared__ float stat;
    float s = x;
#pragma unroll
    for (int o = 16; o; o >>= 1) s += __shfl_xor_sync(0xffffffffu, s, o);
    if (lane == 0) red[w] = s;
    __syncthreads();
    if (t == 0) {
        float m = 0.f;
#pragma unroll
        for (int i = 0; i < 8; i++) m += red[i];
        stat = m * (1.f / 256.f);
    }
    __syncthreads();
    float d = x - stat;
    __syncthreads();
    float vs = d * d;
#pragma unroll
    for (int o = 16; o; o >>= 1) vs += __shfl_xor_sync(0xffffffffu, vs, o);
    if (lane == 0) red[w] = vs;
    __syncthreads();
    if (t == 0) {
        float vv = 0.f;
#pragma unroll
        for (int i = 0; i < 8; i++) vv += red[i];
        stat = rsqrtf(vv * (1.f / 256.f) + 1e-5f);
    }
    __syncthreads();
    float r = d * stat * g[t] + b[t];
    if (BF16OUT) {
        bf16 h = __float2bfloat16(r);
        bf16 l = __float2bfloat16(r - __bfloat162float(h));
        ohi[base] = h;
        olo[base] = l;
    } else {
        if (resid) r += resid[base];
        outf[base] = r;
    }
}

// ---------------------------------------------------------------------------
extern "C" void kernel_launch(void* const* d_in, const int* in_sizes, int n_in,
                              void* d_out, int out_size)
{
    const float* x    = (const float*)d_in[0];
    const float* src  = (const float*)d_in[1];
    const float* Wq   = (const float*)d_in[2];
    const float* Wk   = (const float*)d_in[3];
    const float* Wv   = (const float*)d_in[4];
    const float* Wm   = (const float*)d_in[5];
    const float* W1   = (const float*)d_in[6];
    const float* W2   = (const float*)d_in[7];
    const float* ln1g = (const float*)d_in[8];
    const float* ln1b = (const float*)d_in[9];
    const float* ln2g = (const float*)d_in[10];
    const float* ln2b = (const float*)d_in[11];

    const int C = CDIM;
    const int M = in_sizes[0] / C;
    const int Nb = M / LSEQ;
    const int NH = Nb * NHEADS;

    float *q, *k, *v, *t1f, *kvp, *ksp, *kv, *ksum;
    cudaGetSymbolAddress((void**)&q, g_q);
    cudaGetSymbolAddress((void**)&k, g_k);
    cudaGetSymbolAddress((void**)&v, g_v);
    cudaGetSymbolAddress((void**)&t1f, g_t1f);
    cudaGetSymbolAddress((void**)&kvp, g_kvp);
    cudaGetSymbolAddress((void**)&ksp, g_ksp);
    cudaGetSymbolAddress((void**)&kv, g_kv);
    cudaGetSymbolAddress((void**)&ksum, g_ksum);

    bf16 *xhi, *xlo, *shi, *slo, *mhi, *mlo, *t1hi, *t1lo, *h1hi, *h1lo;
    bf16 *wqh, *wql, *wkh, *wkl, *wvh, *wvl, *wmh, *wml, *w1h, *w1l, *w2h, *w2l;
    cudaGetSymbolAddress((void**)&xhi, g_xhi);   cudaGetSymbolAddress((void**)&xlo, g_xlo);
    cudaGetSymbolAddress((void**)&shi, g_shi);   cudaGetSymbolAddress((void**)&slo, g_slo);
    cudaGetSymbolAddress((void**)&mhi, g_mhi);   cudaGetSymbolAddress((void**)&mlo, g_mlo);
    cudaGetSymbolAddress((void**)&t1hi, g_t1hi); cudaGetSymbolAddress((void**)&t1lo, g_t1lo);
    cudaGetSymbolAddress((void**)&h1hi, g_h1hi); cudaGetSymbolAddress((void**)&h1lo, g_h1lo);
    cudaGetSymbolAddress((void**)&wqh, g_wqhi);  cudaGetSymbolAddress((void**)&wql, g_wqlo);
    cudaGetSymbolAddress((void**)&wkh, g_wkhi);  cudaGetSymbolAddress((void**)&wkl, g_wklo);
    cudaGetSymbolAddress((void**)&wvh, g_wvhi);  cudaGetSymbolAddress((void**)&wvl, g_wvlo);
    cudaGetSymbolAddress((void**)&wmh, g_wmhi);  cudaGetSymbolAddress((void**)&wml, g_wmlo);
    cudaGetSymbolAddress((void**)&w1h, g_w1hi);  cudaGetSymbolAddress((void**)&w1l, g_w1lo);
    cudaGetSymbolAddress((void**)&w2h, g_w2hi);  cudaGetSymbolAddress((void**)&w2l, g_w2lo);

    float* outp = (float*)d_out;

    // input + weight splits
    {
        int n4 = M * C / 4;
        split_kernel<<<(n4 + 255) / 256, 256>>>(x, xhi, xlo, n4);
        split_kernel<<<(n4 + 255) / 256, 256>>>(src, shi, slo, n4);
        int w4 = C * C / 4;
        split_kernel<<<(w4 + 255) / 256, 256>>>(Wq, wqh, wql, w4);
        split_kernel<<<(w4 + 255) / 256, 256>>>(Wk, wkh, wkl, w4);
        split_kernel<<<(w4 + 255) / 256, 256>>>(Wv, wvh, wvl, w4);
        split_kernel<<<(w4 + 255) / 256, 256>>>(Wm, wmh, wml, w4);
        int w14 = 4 * C * C / 4;
        split_kernel<<<(w14 + 255) / 256, 256>>>(W1, w1h, w1l, w14);
        int w24 = 2 * C * C / 4;
        split_kernel<<<(w24 + 255) / 256, 256>>>(W2, w2h, w2l, w24);
    }

    dim3 gq(C / 128, M / 128);
    // q, k, v projections
    gemm_mma<false, 0><<<gq, 256>>>(xhi, xlo, C, xhi, xlo, C, C,
                                    wqh, wql, q, nullptr, nullptr, M, C, C);
    gemm_mma<false, 0><<<gq, 256>>>(shi, slo, C, shi, slo, C, C,
                                    wkh, wkl, k, nullptr, nullptr, M, C, C);
    gemm_mma<false, 0><<<gq, 256>>>(shi, slo, C, shi, slo, C, C,
                                    wvh, wvl, v, nullptr, nullptr, M, C, C);

    // elu+1 and RoPE
    {
        dim3 gr((M * 128 + 255) / 256, 2);
        rope_prep<<<gr, 256>>>(q, k, M);
    }

    // KV / Ksum
    kv_reduce<<<dim3(NCHUNK, NH), 256>>>(k, v, kvp, ksp, NH);
    {
        int tot = NH * 1024 + NH * 32;
        kv_finalize<<<(tot + 255) / 256, 256>>>(kvp, ksp, kv, ksum, NH);
    }

    // attention out -> msg hi/lo
    attn_out<<<M, 256>>>(q, kv, ksum, mhi, mlo);

    // t1 = LN1(msg @ Wm^T) -> hi/lo
    gemm_mma<false, 0><<<gq, 256>>>(mhi, mlo, C, mhi, mlo, C, C,
                                    wmh, wml, t1f, nullptr, nullptr, M, C, C);
    ln_kernel<true><<<M, 256>>>(t1f, ln1g, ln1b, nullptr, nullptr, t1hi, t1lo);

    // h1 = relu([x, t1] @ W1^T) -> hi/lo   (N=512, K=512, Ksplit=256)
    gemm_mma<true, 1><<<dim3(4, M / 128), 256>>>(
        xhi, xlo, C, t1hi, t1lo, C, C,
        w1h, w1l, nullptr, h1hi, h1lo, M, 2 * C, 2 * C);

    // t2 = h1 @ W2^T (reuse q buffer)
    gemm_mma<false, 0><<<gq, 256>>>(h1hi, h1lo, 2 * C, h1hi, h1lo, 2 * C, 2 * C,
                                    w2h, w2l, q, nullptr, nullptr, M, C, 2 * C);

    // out = x + LN2(t2)
    ln_kernel<false><<<M, 256>>>(q, ln2g, ln2b, x, outp, nullptr, nullptr);
}

// round 4
// speedup vs baseline: 2.0894x; 1.0565x over previous
#include <cuda_runtime.h>
#include <cuda_bf16.h>
#include <cstdint>
#include <math.h>

// ---------------------------------------------------------------------------
// RoPE-LoFTR encoder layer. GEMMs via mma.sync bf16 (2-term split, fp32 acc),
// ldmatrix fragment loads, 4-stage cp.async pipeline, RoPE fused in epilogue.
// N=4, L=16384 (128x128), C=256, NHEAD=8, D=32.
// ---------------------------------------------------------------------------

#define MAXM   65536
#define CDIM   256
#define LSEQ   16384
#define NHEADS 8
#define NCHUNK 32

typedef __nv_bfloat16 bf16;

// fp32 buffers
__device__ float g_q  [(size_t)MAXM * CDIM];
__device__ float g_k  [(size_t)MAXM * CDIM];
__device__ float g_v  [(size_t)MAXM * CDIM];
__device__ float g_t1f[(size_t)MAXM * CDIM];
__device__ float g_kvp[(size_t)NCHUNK * 32 * 32 * 32];
__device__ float g_ksp[(size_t)NCHUNK * 32 * 32];
__device__ float g_kv [(size_t)32 * 32 * 32];
__device__ float g_ksum[(size_t)32 * 32];

// bf16 hi/lo buffers
__device__ bf16 g_xhi[(size_t)MAXM * CDIM];
__device__ bf16 g_xlo[(size_t)MAXM * CDIM];
__device__ bf16 g_shi[(size_t)MAXM * CDIM];
__device__ bf16 g_slo[(size_t)MAXM * CDIM];
__device__ bf16 g_mhi[(size_t)MAXM * CDIM];
__device__ bf16 g_mlo[(size_t)MAXM * CDIM];
__device__ bf16 g_t1hi[(size_t)MAXM * CDIM];
__device__ bf16 g_t1lo[(size_t)MAXM * CDIM];
__device__ bf16 g_h1hi[(size_t)MAXM * 2 * CDIM];
__device__ bf16 g_h1lo[(size_t)MAXM * 2 * CDIM];
// weight hi/lo
__device__ bf16 g_wqhi[CDIM * CDIM], g_wqlo[CDIM * CDIM];
__device__ bf16 g_wkhi[CDIM * CDIM], g_wklo[CDIM * CDIM];
__device__ bf16 g_wvhi[CDIM * CDIM], g_wvlo[CDIM * CDIM];
__device__ bf16 g_wmhi[CDIM * CDIM], g_wmlo[CDIM * CDIM];
__device__ bf16 g_w1hi[2 * CDIM * 2 * CDIM], g_w1lo[2 * CDIM * 2 * CDIM];
__device__ bf16 g_w2hi[CDIM * 2 * CDIM], g_w2lo[CDIM * 2 * CDIM];

// ---------------------------------------------------------------------------
#define CP_ASYNC16(dst, src) \
    asm volatile("cp.async.cg.shared.global [%0], [%1], 16;" \
                 :: "r"(dst), "l"(src) : "memory")
#define CP_COMMIT() asm volatile("cp.async.commit_group;" ::: "memory")
#define CP_WAIT(n)  asm volatile("cp.async.wait_group %0;" :: "n"(n) : "memory")

#define LDMATRIX_X4(r0, r1, r2, r3, addr) \
    asm volatile("ldmatrix.sync.aligned.m8n8.x4.shared.b16 {%0,%1,%2,%3}, [%4];" \
                 : "=r"(r0), "=r"(r1), "=r"(r2), "=r"(r3) : "r"(addr))

__device__ __forceinline__ uint32_t smem_u32(const void* p) {
    uint32_t a;
    asm("{ .reg .u64 t; cvta.to.shared.u64 t, %1; cvt.u32.u64 %0, t; }"
        : "=r"(a) : "l"(p));
    return a;
}

__device__ __forceinline__ void mma16816(float* c, const uint32_t* a,
                                         const uint32_t* b) {
    asm volatile(
        "mma.sync.aligned.m16n8k16.row.col.f32.bf16.bf16.f32 "
        "{%0,%1,%2,%3}, {%4,%5,%6,%7}, {%8,%9}, {%0,%1,%2,%3};"
        : "+f"(c[0]), "+f"(c[1]), "+f"(c[2]), "+f"(c[3])
        : "r"(a[0]), "r"(a[1]), "r"(a[2]), "r"(a[3]), "r"(b[0]), "r"(b[1]));
}

// smem tile: 128 rows x 32 bf16 (64B/row); 16B chunk swizzle: ch ^= (row>>1)&3
__device__ __forceinline__ uint32_t tile_off(int row, int ch) {
    return (uint32_t)(row * 64 + ((ch ^ ((row >> 1) & 3)) << 4));
}

__device__ __forceinline__ uint32_t pack_bf16x2(float f0, float f1) {
    bf16 h0 = __float2bfloat16(f0);
    bf16 h1 = __float2bfloat16(f1);
    return (uint32_t)__bfloat16_as_ushort(h1) << 16 |
           (uint32_t)__bfloat16_as_ushort(h0);
}

// ---------------------------------------------------------------------------
// GEMM: C[M,N] = A[M,K] @ B[N,K]^T; A/B bf16 hi/lo; effective K=3K segments:
// seg0 Ahi*Bhi, seg1 Alo*Bhi, seg2 Ahi*Blo. A switches to A2 at k=Ksplit.
// Tile 128x128, BK=32, 256 threads (8 warps, 4m x 2n), 4-stage cp.async ring.
// OMODE 0: fp32 out. OMODE 1: bf16 hi/lo out (after optional RELU).
// OMODE 2: elu+1 then RoPE, fp32 out (for q/k; requires N==256).
// ---------------------------------------------------------------------------
#define STAGES 4
#define STAGE_BYTES 16384

template <int OMODE, bool RELU>
__global__ __launch_bounds__(256) void gemm_mma(
    const bf16* __restrict__ Ahi, const bf16* __restrict__ Alo, int lda,
    const bf16* __restrict__ A2hi, const bf16* __restrict__ A2lo, int lda2,
    int Ksplit,
    const bf16* __restrict__ Bhi, const bf16* __restrict__ Blo,
    float* __restrict__ Cf, bf16* __restrict__ Chi, bf16* __restrict__ Clo,
    int M, int N, int K)
{
    extern __shared__ char smem[];

    const int tid  = threadIdx.x;
    const int lane = tid & 31;
    const int wid  = tid >> 5;
    const int g    = lane >> 2;
    const int tig  = lane & 3;
    const int wm   = wid & 3;
    const int wn   = wid >> 2;
    const int bm   = blockIdx.y * 128;
    const int bn   = blockIdx.x * 128;
    const int kseg = K / 32;
    const int nkc  = 3 * kseg;

    // ldmatrix lane->row/khalf decomposition
    const int a_lrow  = lane & 15;        // A: row within 16
    const int a_khalf = lane >> 4;        // A: k-halves
    const int b_lrow  = lane & 7;         // B: row within 8
    const int b_kpart = (lane >> 3) & 1;
    const int b_npart = lane >> 4;

    float acc[2][8][4];
#pragma unroll
    for (int i = 0; i < 2; i++)
#pragma unroll
        for (int j = 0; j < 8; j++)
#pragma unroll
            for (int e = 0; e < 4; e++) acc[i][j][e] = 0.f;

    const int slot0 = tid, slot1 = tid + 256;

    auto issue = [&](int kc) {
        const int stg = kc & (STAGES - 1);
        const int seg = kc / kseg;
        const int kin = (kc % kseg) * 32;
        const bf16* Asrc; int ald, koff;
        if (kin < Ksplit) { Asrc = (seg == 1) ? Alo  : Ahi;  ald = lda;  koff = kin; }
        else              { Asrc = (seg == 1) ? A2lo : A2hi; ald = lda2; koff = kin - Ksplit; }
        const bf16* Bsrc = (seg == 2) ? Blo : Bhi;

        uint32_t sA = smem_u32(smem + stg * STAGE_BYTES);
        uint32_t sB = sA + 8192;
        {
            int row = slot0 >> 2, ch = slot0 & 3;
            CP_ASYNC16(sA + tile_off(row, ch),
                       Asrc + (size_t)(bm + row) * ald + koff + ch * 8);
        }
        {
            int row = slot1 >> 2, ch = slot1 & 3;
            CP_ASYNC16(sA + tile_off(row, ch),
                       Asrc + (size_t)(bm + row) * ald + koff + ch * 8);
        }
        {
            int row = slot0 >> 2, ch = slot0 & 3;
            CP_ASYNC16(sB + tile_off(row, ch),
                       Bsrc + (size_t)(bn + row) * K + kin + ch * 8);
        }
        {
            int row = slot1 >> 2, ch = slot1 & 3;
            CP_ASYNC16(sB + tile_off(row, ch),
                       Bsrc + (size_t)(bn + row) * K + kin + ch * 8);
        }
        CP_COMMIT();
    };

    issue(0); issue(1); issue(2);

    for (int kc = 0; kc < nkc; kc++) {
        CP_WAIT(2);
        __syncthreads();
        if (kc + 3 < nkc) issue(kc + 3);
        else CP_COMMIT();                 // keep group count consistent

        const uint32_t sA = smem_u32(smem + (kc & (STAGES - 1)) * STAGE_BYTES);
        const uint32_t sB = sA + 8192;

#pragma unroll
        for (int s = 0; s < 2; s++) {
            uint32_t af[2][4];
#pragma unroll
            for (int mi = 0; mi < 2; mi++) {
                int r  = wm * 32 + mi * 16 + a_lrow;
                int ch = 2 * s + a_khalf;
                LDMATRIX_X4(af[mi][0], af[mi][1], af[mi][2], af[mi][3],
                            sA + tile_off(r, ch));
            }
            uint32_t bfr[8][2];
#pragma unroll
            for (int njp = 0; njp < 4; njp++) {
                int r  = wn * 64 + (2 * njp + b_npart) * 8 + b_lrow;
                int ch = 2 * s + b_kpart;
                LDMATRIX_X4(bfr[2 * njp][0], bfr[2 * njp][1],
                            bfr[2 * njp + 1][0], bfr[2 * njp + 1][1],
                            sB + tile_off(r, ch));
            }
#pragma unroll
            for (int mi = 0; mi < 2; mi++)
#pragma unroll
                for (int nj = 0; nj < 8; nj++)
                    mma16816(acc[mi][nj], af[mi], bfr[nj]);
        }
    }

    // epilogue
#pragma unroll
    for (int mi = 0; mi < 2; mi++) {
        int rbase = bm + wm * 32 + mi * 16 + g;
#pragma unroll
        for (int nj = 0; nj < 8; nj++) {
            int col = bn + wn * 64 + nj * 8 + 2 * tig;
            float c0 = acc[mi][nj][0], c1 = acc[mi][nj][1];
            float c2 = acc[mi][nj][2], c3 = acc[mi][nj][3];
            if (OMODE == 2) {
                // elu+1 then RoPE; col is even, (col, col+1) is a rotate pair
                int rem = col >> 1;            // 0..127 (N == 256)
                int tt  = rem & 15;
                int qf  = tt >> 1;
                float dv = expf(-(float)qf * 1.1512925465f);
                bool odd = (tt & 1) != 0;
#pragma unroll
                for (int rr = 0; rr < 2; rr++) {
                    int r = rbase + rr * 8;
                    int l = r & (LSEQ - 1);
                    int ii = l >> 7, jj = l & 127;
                    float pos = odd ? (float)(jj + 1) : (float)(ii + 1);
                    float sn, cs;
                    sincosf(pos * dv, &sn, &cs);
                    float u0 = rr ? c2 : c0;
                    float u1 = rr ? c3 : c1;
                    float x0 = u0 > 0.f ? u0 + 1.f : expf(u0);
                    float x1 = u1 > 0.f ? u1 + 1.f : expf(u1);
                    float2 o;
                    o.x = x0 * cs - x1 * sn;
                    o.y = x1 * cs + x0 * sn;
                    *(float2*)(Cf + (size_t)r * N + col) = o;
                }
            } else {
                if (RELU) {
                    c0 = fmaxf(c0, 0.f); c1 = fmaxf(c1, 0.f);
                    c2 = fmaxf(c2, 0.f); c3 = fmaxf(c3, 0.f);
                }
                if (OMODE == 0) {
                    *(float2*)(Cf + (size_t)rbase * N + col)       = make_float2(c0, c1);
                    *(float2*)(Cf + (size_t)(rbase + 8) * N + col) = make_float2(c2, c3);
                } else {
                    uint32_t h0 = pack_bf16x2(c0, c1);
                    uint32_t h1 = pack_bf16x2(c2, c3);
                    uint32_t l0 = pack_bf16x2(
                        c0 - __bfloat162float(__float2bfloat16(c0)),
                        c1 - __bfloat162float(__float2bfloat16(c1)));
                    uint32_t l1 = pack_bf16x2(
                        c2 - __bfloat162float(__float2bfloat16(c2)),
                        c3 - __bfloat162float(__float2bfloat16(c3)));
                    *(uint32_t*)(Chi + (size_t)rbase * N + col)       = h0;
                    *(uint32_t*)(Chi + (size_t)(rbase + 8) * N + col) = h1;
                    *(uint32_t*)(Clo + (size_t)rbase * N + col)       = l0;
                    *(uint32_t*)(Clo + (size_t)(rbase + 8) * N + col) = l1;
                }
            }
        }
    }
}

// ---------------------------------------------------------------------------
// fp32 -> bf16 hi/lo split
// ---------------------------------------------------------------------------
__global__ __launch_bounds__(256) void split_kernel(const float* __restrict__ in,
                                                    bf16* __restrict__ hi,
                                                    bf16* __restrict__ lo, int n4)
{
    int i = blockIdx.x * 256 + threadIdx.x;
    if (i >= n4) return;
    float4 f = ((const float4*)in)[i];
    float fs[4] = {f.x, f.y, f.z, f.w};
    uint32_t hw[2], lw[2];
#pragma unroll
    for (int j = 0; j < 2; j++) {
        float a = fs[2 * j], b = fs[2 * j + 1];
        bf16 h0 = __float2bfloat16(a);
        bf16 h1 = __float2bfloat16(b);
        hw[j] = (uint32_t)__bfloat16_as_ushort(h1) << 16 |
                (uint32_t)__bfloat16_as_ushort(h0);
        lw[j] = pack_bf16x2(a - __bfloat162float(h0), b - __bfloat162float(h1));
    }
    ((uint2*)hi)[i] = make_uint2(hw[0], hw[1]);
    ((uint2*)lo)[i] = make_uint2(lw[0], lw[1]);
}

// ---------------------------------------------------------------------------
// KV / Ksum chunked reduction (deterministic), then finalize
// ---------------------------------------------------------------------------
__global__ __launch_bounds__(256) void kv_reduce(
    const float* __restrict__ Kr, const float* __restrict__ V,
    float* __restrict__ kvp, float* __restrict__ ksp, int NH)
{
    int chunk = blockIdx.x, nh = blockIdx.y;
    int n = nh >> 3, h = nh & 7;
    int t = threadIdx.x, d = t & 31, eg = t >> 5;
    const int rows = LSEQ / NCHUNK;
    int s0 = chunk * rows;
    __shared__ float Ks[8][32], Vs[8][32];
    float a0 = 0.f, a1 = 0.f, a2 = 0.f, a3 = 0.f, ks = 0.f;
    int ls = t >> 5, ld = t & 31;
    for (int s = 0; s < rows; s += 8) {
        size_t off = (size_t)(n * LSEQ + s0 + s + ls) * CDIM + h * 32 + ld;
        Ks[ls][ld] = Kr[off];
        Vs[ls][ld] = V[off];
        __syncthreads();
#pragma unroll
        for (int ss = 0; ss < 8; ss++) {
            float kd = Ks[ss][d];
            if (eg == 0) ks += kd;
            const float* vr = &Vs[ss][eg * 4];
            a0 += kd * vr[0]; a1 += kd * vr[1];
            a2 += kd * vr[2]; a3 += kd * vr[3];
        }
        __syncthreads();
    }
    size_t pbase = ((size_t)(chunk * NH + nh) * 32 + d) * 32 + eg * 4;
    kvp[pbase + 0] = a0; kvp[pbase + 1] = a1;
    kvp[pbase + 2] = a2; kvp[pbase + 3] = a3;
    if (eg == 0) ksp[(size_t)(chunk * NH + nh) * 32 + d] = ks;
}

__global__ void kv_finalize(const float* __restrict__ kvp, const float* __restrict__ ksp,
                            float* __restrict__ kv, float* __restrict__ ksum, int NH)
{
    int i = blockIdx.x * blockDim.x + threadIdx.x;
    int tot_kv = NH * 1024, tot_ks = NH * 32;
    if (i < tot_kv) {
        float s = 0.f;
        for (int c = 0; c < NCHUNK; c++) s += kvp[(size_t)c * tot_kv + i];
        kv[i] = s;
    } else if (i < tot_kv + tot_ks) {
        int j = i - tot_kv;
        float s = 0.f;
        for (int c = 0; c < NCHUNK; c++) s += ksp[(size_t)c * tot_ks + j];
        ksum[j] = s;
    }
}

// ---------------------------------------------------------------------------
// attention output per (token, head); writes msg as bf16 hi/lo
// ---------------------------------------------------------------------------
__global__ __launch_bounds__(256) void attn_out(
    const float* __restrict__ Q, const float* __restrict__ KV,
    const float* __restrict__ Ksum, bf16* __restrict__ mhi, bf16* __restrict__ mlo)
{
    int m = blockIdx.x, w = threadIdx.x >> 5, lane = threadIdx.x & 31;
    int n = m / LSEQ, nh = n * NHEADS + w;
    float qv = Q[(size_t)m * CDIM + w * 32 + lane];
    float z = qv * Ksum[nh * 32 + lane];
#pragma unroll
    for (int o = 16; o; o >>= 1) z += __shfl_xor_sync(0xffffffffu, z, o);
    float Z = 1.f / (z + 1e-6f);
    const float* kvh = KV + (size_t)nh * 1024;
    float acc = 0.f;
#pragma unroll
    for (int d = 0; d < 32; d++)
        acc += __shfl_sync(0xffffffffu, qv, d) * kvh[d * 32 + lane];
    float r = acc * Z;
    bf16 h = __float2bfloat16(r);
    bf16 l = __float2bfloat16(r - __bfloat162float(h));
    size_t off = (size_t)m * CDIM + w * 32 + lane;
    mhi[off] = h;
    mlo[off] = l;
}

// ---------------------------------------------------------------------------
// LayerNorm over C=256. BF16OUT: write hi/lo. Else fp32 (+optional residual).
// ---------------------------------------------------------------------------
template <bool BF16OUT>
__global__ __launch_bounds__(256) void ln_kernel(
    const float* __restrict__ in, const float* __restrict__ g,
    const float* __restrict__ b, const float* __restrict__ resid,
    float* __restrict__ outf, bf16* __restrict__ ohi, bf16* __restrict__ olo)
{
    int row = blockIdx.x, t = threadIdx.x;
    int lane = t & 31, w = t >> 5;
    size_t base = (size_t)row * CDIM + t;
    float x = in[base];
    __shared__ float red[8];
    __shared__ float stat;
    float s = x;
#pragma unroll
    for (int o = 16; o; o >>= 1) s += __shfl_xor_sync(0xffffffffu, s, o);
    if (lane == 0) red[w] = s;
    __syncthreads();
    if (t == 0) {
        float m = 0.f;
#pragma unroll
        for (int i = 0; i < 8; i++) m += red[i];
        stat = m * (1.f / 256.f);
    }
    __syncthreads();
    float d = x - stat;
    __syncthreads();
    float vs = d * d;
#pragma unroll
    for (int o = 16; o; o >>= 1) vs += __shfl_xor_sync(0xffffffffu, vs, o);
    if (lane == 0) red[w] = vs;
    __syncthreads();
    if (t == 0) {
        float vv = 0.f;
#pragma unroll
        for (int i = 0; i < 8; i++) vv += red[i];
        stat = rsqrtf(vv * (1.f / 256.f) + 1e-5f);
    }
    __syncthreads();
    float r = d * stat * g[t] + b[t];
    if (BF16OUT) {
        bf16 h = __float2bfloat16(r);
        bf16 l = __float2bfloat16(r - __bfloat162float(h));
        ohi[base] = h;
        olo[base] = l;
    } else {
        if (resid) r += resid[base];
        outf[base] = r;
    }
}

// ---------------------------------------------------------------------------
extern "C" void kernel_launch(void* const* d_in, const int* in_sizes, int n_in,
                              void* d_out, int out_size)
{
    const float* x    = (const float*)d_in[0];
    const float* src  = (const float*)d_in[1];
    const float* Wq   = (const float*)d_in[2];
    const float* Wk   = (const float*)d_in[3];
    const float* Wv   = (const float*)d_in[4];
    const float* Wm   = (const float*)d_in[5];
    const float* W1   = (const float*)d_in[6];
    const float* W2   = (const float*)d_in[7];
    const float* ln1g = (const float*)d_in[8];
    const float* ln1b = (const float*)d_in[9];
    const float* ln2g = (const float*)d_in[10];
    const float* ln2b = (const float*)d_in[11];

    const int C = CDIM;
    const int M = in_sizes[0] / C;
    const int Nb = M / LSEQ;
    const int NH = Nb * NHEADS;

    float *q, *k, *v, *t1f, *kvp, *ksp, *kv, *ksum;
    cudaGetSymbolAddress((void**)&q, g_q);
    cudaGetSymbolAddress((void**)&k, g_k);
    cudaGetSymbolAddress((void**)&v, g_v);
    cudaGetSymbolAddress((void**)&t1f, g_t1f);
    cudaGetSymbolAddress((void**)&kvp, g_kvp);
    cudaGetSymbolAddress((void**)&ksp, g_ksp);
    cudaGetSymbolAddress((void**)&kv, g_kv);
    cudaGetSymbolAddress((void**)&ksum, g_ksum);

    bf16 *xhi, *xlo, *shi, *slo, *mhi, *mlo, *t1hi, *t1lo, *h1hi, *h1lo;
    bf16 *wqh, *wql, *wkh, *wkl, *wvh, *wvl, *wmh, *wml, *w1h, *w1l, *w2h, *w2l;
    cudaGetSymbolAddress((void**)&xhi, g_xhi);   cudaGetSymbolAddress((void**)&xlo, g_xlo);
    cudaGetSymbolAddress((void**)&shi, g_shi);   cudaGetSymbolAddress((void**)&slo, g_slo);
    cudaGetSymbolAddress((void**)&mhi, g_mhi);   cudaGetSymbolAddress((void**)&mlo, g_mlo);
    cudaGetSymbolAddress((void**)&t1hi, g_t1hi); cudaGetSymbolAddress((void**)&t1lo, g_t1lo);
    cudaGetSymbolAddress((void**)&h1hi, g_h1hi); cudaGetSymbolAddress((void**)&h1lo, g_h1lo);
    cudaGetSymbolAddress((void**)&wqh, g_wqhi);  cudaGetSymbolAddress((void**)&wql, g_wqlo);
    cudaGetSymbolAddress((void**)&wkh, g_wkhi);  cudaGetSymbolAddress((void**)&wkl, g_wklo);
    cudaGetSymbolAddress((void**)&wvh, g_wvhi);  cudaGetSymbolAddress((void**)&wvl, g_wvlo);
    cudaGetSymbolAddress((void**)&wmh, g_wmhi);  cudaGetSymbolAddress((void**)&wml, g_wmlo);
    cudaGetSymbolAddress((void**)&w1h, g_w1hi);  cudaGetSymbolAddress((void**)&w1l, g_w1lo);
    cudaGetSymbolAddress((void**)&w2h, g_w2hi);  cudaGetSymbolAddress((void**)&w2l, g_w2lo);

    float* outp = (float*)d_out;

    const int DSMEM = STAGES * STAGE_BYTES;
    cudaFuncSetAttribute(gemm_mma<0, false>, cudaFuncAttributeMaxDynamicSharedMemorySize, DSMEM);
    cudaFuncSetAttribute(gemm_mma<1, true>,  cudaFuncAttributeMaxDynamicSharedMemorySize, DSMEM);
    cudaFuncSetAttribute(gemm_mma<2, false>, cudaFuncAttributeMaxDynamicSharedMemorySize, DSMEM);

    // input + weight splits
    {
        int n4 = M * C / 4;
        split_kernel<<<(n4 + 255) / 256, 256>>>(x, xhi, xlo, n4);
        split_kernel<<<(n4 + 255) / 256, 256>>>(src, shi, slo, n4);
        int w4 = C * C / 4;
        split_kernel<<<(w4 + 255) / 256, 256>>>(Wq, wqh, wql, w4);
        split_kernel<<<(w4 + 255) / 256, 256>>>(Wk, wkh, wkl, w4);
        split_kernel<<<(w4 + 255) / 256, 256>>>(Wv, wvh, wvl, w4);
        split_kernel<<<(w4 + 255) / 256, 256>>>(Wm, wmh, wml, w4);
        int w14 = 4 * C * C / 4;
        split_kernel<<<(w14 + 255) / 256, 256>>>(W1, w1h, w1l, w14);
        int w24 = 2 * C * C / 4;
        split_kernel<<<(w24 + 255) / 256, 256>>>(W2, w2h, w2l, w24);
    }

    dim3 gq(C / 128, M / 128);
    // q, k projections with fused elu+1 + RoPE; v plain fp32
    gemm_mma<2, false><<<gq, 256, DSMEM>>>(xhi, xlo, C, xhi, xlo, C, C,
                                           wqh, wql, q, nullptr, nullptr, M, C, C);
    gemm_mma<2, false><<<gq, 256, DSMEM>>>(shi, slo, C, shi, slo, C, C,
                                           wkh, wkl, k, nullptr, nullptr, M, C, C);
    gemm_mma<0, false><<<gq, 256, DSMEM>>>(shi, slo, C, shi, slo, C, C,
                                           wvh, wvl, v, nullptr, nullptr, M, C, C);

    // KV / Ksum
    kv_reduce<<<dim3(NCHUNK, NH), 256>>>(k, v, kvp, ksp, NH);
    {
        int tot = NH * 1024 + NH * 32;
        kv_finalize<<<(tot + 255) / 256, 256>>>(kvp, ksp, kv, ksum, NH);
    }

    // attention out -> msg hi/lo
    attn_out<<<M, 256>>>(q, kv, ksum, mhi, mlo);

    // t1 = LN1(msg @ Wm^T) -> hi/lo
    gemm_mma<0, false><<<gq, 256, DSMEM>>>(mhi, mlo, C, mhi, mlo, C, C,
                                           wmh, wml, t1f, nullptr, nullptr, M, C, C);
    ln_kernel<true><<<M, 256>>>(t1f, ln1g, ln1b, nullptr, nullptr, t1hi, t1lo);

    // h1 = relu([x, t1] @ W1^T) -> hi/lo   (N=512, K=512, Ksplit=256)
    gemm_mma<1, true><<<dim3(4, M / 128), 256, DSMEM>>>(
        xhi, xlo, C, t1hi, t1lo, C, C,
        w1h, w1l, nullptr, h1hi, h1lo, M, 2 * C, 2 * C);

    // t2 = h1 @ W2^T (reuse q buffer)
    gemm_mma<0, false><<<gq, 256, DSMEM>>>(h1hi, h1lo, 2 * C, h1hi, h1lo, 2 * C, 2 * C,
                                           w2h, w2l, q, nullptr, nullptr, M, C, 2 * C);

    // out = x + LN2(t2)
    ln_kernel<false><<<M, 256>>>(q, ln2g, ln2b, x, outp, nullptr, nullptr);
}

// round 5
// speedup vs baseline: 2.6480x; 1.2674x over previous
#include <cuda_runtime.h>
#include <cuda_fp16.h>
#include <cstdint>
#include <math.h>

// ---------------------------------------------------------------------------
// RoPE-LoFTR encoder layer. GEMMs via mma.sync fp16 (activation 2-term split,
// weights single fp16, fp32 accum), ldmatrix loads, 4-stage cp.async ring,
// RoPE fused into q/k GEMM epilogues.
// N=4, L=16384 (128x128), C=256, NHEAD=8, D=32.
// ---------------------------------------------------------------------------

#define MAXM   65536
#define CDIM   256
#define LSEQ   16384
#define NHEADS 8
#define NCHUNK 32

typedef __half hf;

// fp32 buffers
__device__ float g_q  [(size_t)MAXM * CDIM];
__device__ float g_k  [(size_t)MAXM * CDIM];
__device__ float g_v  [(size_t)MAXM * CDIM];
__device__ float g_t1f[(size_t)MAXM * CDIM];
__device__ float g_kvp[(size_t)NCHUNK * 32 * 32 * 32];
__device__ float g_ksp[(size_t)NCHUNK * 32 * 32];
__device__ float g_kv [(size_t)32 * 32 * 32];
__device__ float g_ksum[(size_t)32 * 32];

// fp16 hi/lo activation buffers
__device__ hf g_xhi[(size_t)MAXM * CDIM];
__device__ hf g_xlo[(size_t)MAXM * CDIM];
__device__ hf g_shi[(size_t)MAXM * CDIM];
__device__ hf g_slo[(size_t)MAXM * CDIM];
__device__ hf g_mhi[(size_t)MAXM * CDIM];
__device__ hf g_mlo[(size_t)MAXM * CDIM];
__device__ hf g_t1hi[(size_t)MAXM * CDIM];
__device__ hf g_t1lo[(size_t)MAXM * CDIM];
__device__ hf g_h1hi[(size_t)MAXM * 2 * CDIM];
__device__ hf g_h1lo[(size_t)MAXM * 2 * CDIM];
// fp16 weights (single precision term)
__device__ hf g_wq[CDIM * CDIM];
__device__ hf g_wk[CDIM * CDIM];
__device__ hf g_wv[CDIM * CDIM];
__device__ hf g_wm[CDIM * CDIM];
__device__ hf g_w1[2 * CDIM * 2 * CDIM];
__device__ hf g_w2[CDIM * 2 * CDIM];

// ---------------------------------------------------------------------------
#define CP_ASYNC16(dst, src) \
    asm volatile("cp.async.cg.shared.global [%0], [%1], 16;" \
                 :: "r"(dst), "l"(src) : "memory")
#define CP_COMMIT() asm volatile("cp.async.commit_group;" ::: "memory")
#define CP_WAIT(n)  asm volatile("cp.async.wait_group %0;" :: "n"(n) : "memory")

#define LDMATRIX_X4(r0, r1, r2, r3, addr) \
    asm volatile("ldmatrix.sync.aligned.m8n8.x4.shared.b16 {%0,%1,%2,%3}, [%4];" \
                 : "=r"(r0), "=r"(r1), "=r"(r2), "=r"(r3) : "r"(addr))

__device__ __forceinline__ uint32_t smem_u32(const void* p) {
    uint32_t a;
    asm("{ .reg .u64 t; cvta.to.shared.u64 t, %1; cvt.u32.u64 %0, t; }"
        : "=r"(a) : "l"(p));
    return a;
}

__device__ __forceinline__ void mma16816(float* c, const uint32_t* a,
                                         const uint32_t* b) {
    asm volatile(
        "mma.sync.aligned.m16n8k16.row.col.f32.f16.f16.f32 "
        "{%0,%1,%2,%3}, {%4,%5,%6,%7}, {%8,%9}, {%0,%1,%2,%3};"
        : "+f"(c[0]), "+f"(c[1]), "+f"(c[2]), "+f"(c[3])
        : "r"(a[0]), "r"(a[1]), "r"(a[2]), "r"(a[3]), "r"(b[0]), "r"(b[1]));
}

// smem tile: 128 rows x 32 fp16 (64B/row); 16B chunk swizzle: ch ^= (row>>1)&3
__device__ __forceinline__ uint32_t tile_off(int row, int ch) {
    return (uint32_t)(row * 64 + ((ch ^ ((row >> 1) & 3)) << 4));
}

__device__ __forceinline__ uint32_t pack_h2(float f0, float f1) {
    hf h0 = __float2half_rn(f0);
    hf h1 = __float2half_rn(f1);
    return (uint32_t)__half_as_ushort(h1) << 16 |
           (uint32_t)__half_as_ushort(h0);
}

// ---------------------------------------------------------------------------
// GEMM: C[M,N] = A[M,K] @ B[N,K]^T; A fp16 hi/lo, B fp16; effective K=2K:
// seg0 Ahi*B, seg1 Alo*B. A switches to A2 at k=Ksplit (concat GEMM).
// Tile 128x128, BK=32, 256 threads (8 warps, 4m x 2n), 4-stage cp.async ring.
// OMODE 0: fp32 out. OMODE 1: fp16 hi/lo out (after optional RELU).
// OMODE 2: elu+1 then RoPE, fp32 out (for q/k; requires N==256).
// ---------------------------------------------------------------------------
#define STAGES 4
#define STAGE_BYTES 16384

template <int OMODE, bool RELU>
__global__ __launch_bounds__(256) void gemm_mma(
    const hf* __restrict__ Ahi, const hf* __restrict__ Alo, int lda,
    const hf* __restrict__ A2hi, const hf* __restrict__ A2lo, int lda2,
    int Ksplit,
    const hf* __restrict__ B,
    float* __restrict__ Cf, hf* __restrict__ Chi, hf* __restrict__ Clo,
    int M, int N, int K)
{
    extern __shared__ char smem[];

    const int tid  = threadIdx.x;
    const int lane = tid & 31;
    const int wid  = tid >> 5;
    const int g    = lane >> 2;
    const int tig  = lane & 3;
    const int wm   = wid & 3;
    const int wn   = wid >> 2;
    const int bm   = blockIdx.y * 128;
    const int bn   = blockIdx.x * 128;
    const int kseg = K / 32;
    const int nkc  = 2 * kseg;

    const int a_lrow  = lane & 15;
    const int a_khalf = lane >> 4;
    const int b_lrow  = lane & 7;
    const int b_kpart = (lane >> 3) & 1;
    const int b_npart = lane >> 4;

    float acc[2][8][4];
#pragma unroll
    for (int i = 0; i < 2; i++)
#pragma unroll
        for (int j = 0; j < 8; j++)
#pragma unroll
            for (int e = 0; e < 4; e++) acc[i][j][e] = 0.f;

    const int slot0 = tid, slot1 = tid + 256;

    auto issue = [&](int kc) {
        const int stg = kc & (STAGES - 1);
        const int seg = kc / kseg;          // 0: hi, 1: lo
        const int kin = (kc % kseg) * 32;
        const hf* Asrc; int ald, koff;
        if (kin < Ksplit) { Asrc = seg ? Alo  : Ahi;  ald = lda;  koff = kin; }
        else              { Asrc = seg ? A2lo : A2hi; ald = lda2; koff = kin - Ksplit; }

        uint32_t sA = smem_u32(smem + stg * STAGE_BYTES);
        uint32_t sB = sA + 8192;
        {
            int row = slot0 >> 2, ch = slot0 & 3;
            CP_ASYNC16(sA + tile_off(row, ch),
                       Asrc + (size_t)(bm + row) * ald + koff + ch * 8);
        }
        {
            int row = slot1 >> 2, ch = slot1 & 3;
            CP_ASYNC16(sA + tile_off(row, ch),
                       Asrc + (size_t)(bm + row) * ald + koff + ch * 8);
        }
        {
            int row = slot0 >> 2, ch = slot0 & 3;
            CP_ASYNC16(sB + tile_off(row, ch),
                       B + (size_t)(bn + row) * K + kin + ch * 8);
        }
        {
            int row = slot1 >> 2, ch = slot1 & 3;
            CP_ASYNC16(sB + tile_off(row, ch),
                       B + (size_t)(bn + row) * K + kin + ch * 8);
        }
        CP_COMMIT();
    };

    issue(0); issue(1); issue(2);

    for (int kc = 0; kc < nkc; kc++) {
        CP_WAIT(2);
        __syncthreads();
        if (kc + 3 < nkc) issue(kc + 3);
        else CP_COMMIT();                 // keep group count consistent

        const uint32_t sA = smem_u32(smem + (kc & (STAGES - 1)) * STAGE_BYTES);
        const uint32_t sB = sA + 8192;

#pragma unroll
        for (int s = 0; s < 2; s++) {
            uint32_t af[2][4];
#pragma unroll
            for (int mi = 0; mi < 2; mi++) {
                int r  = wm * 32 + mi * 16 + a_lrow;
                int ch = 2 * s + a_khalf;
                LDMATRIX_X4(af[mi][0], af[mi][1], af[mi][2], af[mi][3],
                            sA + tile_off(r, ch));
            }
            uint32_t bfr[8][2];
#pragma unroll
            for (int njp = 0; njp < 4; njp++) {
                int r  = wn * 64 + (2 * njp + b_npart) * 8 + b_lrow;
                int ch = 2 * s + b_kpart;
                LDMATRIX_X4(bfr[2 * njp][0], bfr[2 * njp][1],
                            bfr[2 * njp + 1][0], bfr[2 * njp + 1][1],
                            sB + tile_off(r, ch));
            }
#pragma unroll
            for (int mi = 0; mi < 2; mi++)
#pragma unroll
                for (int nj = 0; nj < 8; nj++)
                    mma16816(acc[mi][nj], af[mi], bfr[nj]);
        }
    }

    // epilogue
#pragma unroll
    for (int mi = 0; mi < 2; mi++) {
        int rbase = bm + wm * 32 + mi * 16 + g;
#pragma unroll
        for (int nj = 0; nj < 8; nj++) {
            int col = bn + wn * 64 + nj * 8 + 2 * tig;
            float c0 = acc[mi][nj][0], c1 = acc[mi][nj][1];
            float c2 = acc[mi][nj][2], c3 = acc[mi][nj][3];
            if (OMODE == 2) {
                // elu+1 then RoPE; col is even, (col, col+1) is a rotate pair
                int rem = col >> 1;            // 0..127 (N == 256)
                int tt  = rem & 15;
                int qf  = tt >> 1;
                float dv = expf(-(float)qf * 1.1512925465f);
                bool odd = (tt & 1) != 0;
#pragma unroll
                for (int rr = 0; rr < 2; rr++) {
                    int r = rbase + rr * 8;
                    int l = r & (LSEQ - 1);
                    int ii = l >> 7, jj = l & 127;
                    float pos = odd ? (float)(jj + 1) : (float)(ii + 1);
                    float sn, cs;
                    sincosf(pos * dv, &sn, &cs);
                    float u0 = rr ? c2 : c0;
                    float u1 = rr ? c3 : c1;
                    float x0 = u0 > 0.f ? u0 + 1.f : expf(u0);
                    float x1 = u1 > 0.f ? u1 + 1.f : expf(u1);
                    float2 o;
                    o.x = x0 * cs - x1 * sn;
                    o.y = x1 * cs + x0 * sn;
                    *(float2*)(Cf + (size_t)r * N + col) = o;
                }
            } else {
                if (RELU) {
                    c0 = fmaxf(c0, 0.f); c1 = fmaxf(c1, 0.f);
                    c2 = fmaxf(c2, 0.f); c3 = fmaxf(c3, 0.f);
                }
                if (OMODE == 0) {
                    *(float2*)(Cf + (size_t)rbase * N + col)       = make_float2(c0, c1);
                    *(float2*)(Cf + (size_t)(rbase + 8) * N + col) = make_float2(c2, c3);
                } else {
                    uint32_t h0 = pack_h2(c0, c1);
                    uint32_t h1 = pack_h2(c2, c3);
                    uint32_t l0 = pack_h2(
                        c0 - __half2float(__float2half_rn(c0)),
                        c1 - __half2float(__float2half_rn(c1)));
                    uint32_t l1 = pack_h2(
                        c2 - __half2float(__float2half_rn(c2)),
                        c3 - __half2float(__float2half_rn(c3)));
                    *(uint32_t*)(Chi + (size_t)rbase * N + col)       = h0;
                    *(uint32_t*)(Chi + (size_t)(rbase + 8) * N + col) = h1;
                    *(uint32_t*)(Clo + (size_t)rbase * N + col)       = l0;
                    *(uint32_t*)(Clo + (size_t)(rbase + 8) * N + col) = l1;
                }
            }
        }
    }
}

// ---------------------------------------------------------------------------
// fp32 -> fp16 hi/lo split
// ---------------------------------------------------------------------------
__global__ __launch_bounds__(256) void split_kernel(const float* __restrict__ in,
                                                    hf* __restrict__ hi,
                                                    hf* __restrict__ lo, int n4)
{
    int i = blockIdx.x * 256 + threadIdx.x;
    if (i >= n4) return;
    float4 f = ((const float4*)in)[i];
    float fs[4] = {f.x, f.y, f.z, f.w};
    uint32_t hw[2], lw[2];
#pragma unroll
    for (int j = 0; j < 2; j++) {
        float a = fs[2 * j], b = fs[2 * j + 1];
        hf h0 = __float2half_rn(a);
        hf h1 = __float2half_rn(b);
        hw[j] = (uint32_t)__half_as_ushort(h1) << 16 |
                (uint32_t)__half_as_ushort(h0);
        lw[j] = pack_h2(a - __half2float(h0), b - __half2float(h1));
    }
    ((uint2*)hi)[i] = make_uint2(hw[0], hw[1]);
    ((uint2*)lo)[i] = make_uint2(lw[0], lw[1]);
}

// fp32 -> fp16 convert (weights, single term)
__global__ __launch_bounds__(256) void wconv_kernel(const float* __restrict__ in,
                                                    hf* __restrict__ out, int n4)
{
    int i = blockIdx.x * 256 + threadIdx.x;
    if (i >= n4) return;
    float4 f = ((const float4*)in)[i];
    uint2 o;
    o.x = pack_h2(f.x, f.y);
    o.y = pack_h2(f.z, f.w);
    ((uint2*)out)[i] = o;
}

// ---------------------------------------------------------------------------
// KV / Ksum chunked reduction (deterministic), then finalize
// ---------------------------------------------------------------------------
__global__ __launch_bounds__(256) void kv_reduce(
    const float* __restrict__ Kr, const float* __restrict__ V,
    float* __restrict__ kvp, float* __restrict__ ksp, int NH)
{
    int chunk = blockIdx.x, nh = blockIdx.y;
    int n = nh >> 3, h = nh & 7;
    int t = threadIdx.x, d = t & 31, eg = t >> 5;
    const int rows = LSEQ / NCHUNK;
    int s0 = chunk * rows;
    __shared__ float Ks[8][32], Vs[8][32];
    float a0 = 0.f, a1 = 0.f, a2 = 0.f, a3 = 0.f, ks = 0.f;
    int ls = t >> 5, ld = t & 31;
    for (int s = 0; s < rows; s += 8) {
        size_t off = (size_t)(n * LSEQ + s0 + s + ls) * CDIM + h * 32 + ld;
        Ks[ls][ld] = Kr[off];
        Vs[ls][ld] = V[off];
        __syncthreads();
#pragma unroll
        for (int ss = 0; ss < 8; ss++) {
            float kd = Ks[ss][d];
            if (eg == 0) ks += kd;
            const float* vr = &Vs[ss][eg * 4];
            a0 += kd * vr[0]; a1 += kd * vr[1];
            a2 += kd * vr[2]; a3 += kd * vr[3];
        }
        __syncthreads();
    }
    size_t pbase = ((size_t)(chunk * NH + nh) * 32 + d) * 32 + eg * 4;
    kvp[pbase + 0] = a0; kvp[pbase + 1] = a1;
    kvp[pbase + 2] = a2; kvp[pbase + 3] = a3;
    if (eg == 0) ksp[(size_t)(chunk * NH + nh) * 32 + d] = ks;
}

__global__ void kv_finalize(const float* __restrict__ kvp, const float* __restrict__ ksp,
                            float* __restrict__ kv, float* __restrict__ ksum, int NH)
{
    int i = blockIdx.x * blockDim.x + threadIdx.x;
    int tot_kv = NH * 1024, tot_ks = NH * 32;
    if (i < tot_kv) {
        float s = 0.f;
        for (int c = 0; c < NCHUNK; c++) s += kvp[(size_t)c * tot_kv + i];
        kv[i] = s;
    } else if (i < tot_kv + tot_ks) {
        int j = i - tot_kv;
        float s = 0.f;
        for (int c = 0; c < NCHUNK; c++) s += ksp[(size_t)c * tot_ks + j];
        ksum[j] = s;
    }
}

// ---------------------------------------------------------------------------
// attention output per (token, head); writes msg as fp16 hi/lo
// ---------------------------------------------------------------------------
__global__ __launch_bounds__(256) void attn_out(
    const float* __restrict__ Q, const float* __restrict__ KV,
    const float* __restrict__ Ksum, hf* __restrict__ mhi, hf* __restrict__ mlo)
{
    int m = blockIdx.x, w = threadIdx.x >> 5, lane = threadIdx.x & 31;
    int n = m / LSEQ, nh = n * NHEADS + w;
    float qv = Q[(size_t)m * CDIM + w * 32 + lane];
    float z = qv * Ksum[nh * 32 + lane];
#pragma unroll
    for (int o = 16; o; o >>= 1) z += __shfl_xor_sync(0xffffffffu, z, o);
    float Z = 1.f / (z + 1e-6f);
    const float* kvh = KV + (size_t)nh * 1024;
    float acc = 0.f;
#pragma unroll
    for (int d = 0; d < 32; d++)
        acc += __shfl_sync(0xffffffffu, qv, d) * kvh[d * 32 + lane];
    float r = acc * Z;
    hf h = __float2half_rn(r);
    hf l = __float2half_rn(r - __half2float(h));
    size_t off = (size_t)m * CDIM + w * 32 + lane;
    mhi[off] = h;
    mlo[off] = l;
}

// ---------------------------------------------------------------------------
// LayerNorm over C=256. HOUT: write fp16 hi/lo. Else fp32 (+optional residual).
// ---------------------------------------------------------------------------
template <bool HOUT>
__global__ __launch_bounds__(256) void ln_kernel(
    const float* __restrict__ in, const float* __restrict__ g,
    const float* __restrict__ b, const float* __restrict__ resid,
    float* __restrict__ outf, hf* __restrict__ ohi, hf* __restrict__ olo)
{
    int row = blockIdx.x, t = threadIdx.x;
    int lane = t & 31, w = t >> 5;
    size_t base = (size_t)row * CDIM + t;
    float x = in[base];
    __shared__ float red[8];
    __shared__ float stat;
    float s = x;
#pragma unroll
    for (int o = 16; o; o >>= 1) s += __shfl_xor_sync(0xffffffffu, s, o);
    if (lane == 0) red[w] = s;
    __syncthreads();
    if (t == 0) {
        float m = 0.f;
#pragma unroll
        for (int i = 0; i < 8; i++) m += red[i];
        stat = m * (1.f / 256.f);
    }
    __syncthreads();
    float d = x - stat;
    __syncthreads();
    float vs = d * d;
#pragma unroll
    for (int o = 16; o; o >>= 1) vs += __shfl_xor_sync(0xffffffffu, vs, o);
    if (lane == 0) red[w] = vs;
    __syncthreads();
    if (t == 0) {
        float vv = 0.f;
#pragma unroll
        for (int i = 0; i < 8; i++) vv += red[i];
        stat = rsqrtf(vv * (1.f / 256.f) + 1e-5f);
    }
    __syncthreads();
    float r = d * stat * g[t] + b[t];
    if (HOUT) {
        hf h = __float2half_rn(r);
        hf l = __float2half_rn(r - __half2float(h));
        ohi[base] = h;
        olo[base] = l;
    } else {
        if (resid) r += resid[base];
        outf[base] = r;
    }
}

// ---------------------------------------------------------------------------
extern "C" void kernel_launch(void* const* d_in, const int* in_sizes, int n_in,
                              void* d_out, int out_size)
{
    const float* x    = (const float*)d_in[0];
    const float* src  = (const float*)d_in[1];
    const float* Wq   = (const float*)d_in[2];
    const float* Wk   = (const float*)d_in[3];
    const float* Wv   = (const float*)d_in[4];
    const float* Wm   = (const float*)d_in[5];
    const float* W1   = (const float*)d_in[6];
    const float* W2   = (const float*)d_in[7];
    const float* ln1g = (const float*)d_in[8];
    const float* ln1b = (const float*)d_in[9];
    const float* ln2g = (const float*)d_in[10];
    const float* ln2b = (const float*)d_in[11];

    const int C = CDIM;
    const int M = in_sizes[0] / C;
    const int Nb = M / LSEQ;
    const int NH = Nb * NHEADS;

    float *q, *k, *v, *t1f, *kvp, *ksp, *kv, *ksum;
    cudaGetSymbolAddress((void**)&q, g_q);
    cudaGetSymbolAddress((void**)&k, g_k);
    cudaGetSymbolAddress((void**)&v, g_v);
    cudaGetSymbolAddress((void**)&t1f, g_t1f);
    cudaGetSymbolAddress((void**)&kvp, g_kvp);
    cudaGetSymbolAddress((void**)&ksp, g_ksp);
    cudaGetSymbolAddress((void**)&kv, g_kv);
    cudaGetSymbolAddress((void**)&ksum, g_ksum);

    hf *xhi, *xlo, *shi, *slo, *mhi, *mlo, *t1hi, *t1lo, *h1hi, *h1lo;
    hf *wq, *wk, *wv, *wm, *w1, *w2;
    cudaGetSymbolAddress((void**)&xhi, g_xhi);   cudaGetSymbolAddress((void**)&xlo, g_xlo);
    cudaGetSymbolAddress((void**)&shi, g_shi);   cudaGetSymbolAddress((void**)&slo, g_slo);
    cudaGetSymbolAddress((void**)&mhi, g_mhi);   cudaGetSymbolAddress((void**)&mlo, g_mlo);
    cudaGetSymbolAddress((void**)&t1hi, g_t1hi); cudaGetSymbolAddress((void**)&t1lo, g_t1lo);
    cudaGetSymbolAddress((void**)&h1hi, g_h1hi); cudaGetSymbolAddress((void**)&h1lo, g_h1lo);
    cudaGetSymbolAddress((void**)&wq, g_wq);
    cudaGetSymbolAddress((void**)&wk, g_wk);
    cudaGetSymbolAddress((void**)&wv, g_wv);
    cudaGetSymbolAddress((void**)&wm, g_wm);
    cudaGetSymbolAddress((void**)&w1, g_w1);
    cudaGetSymbolAddress((void**)&w2, g_w2);

    float* outp = (float*)d_out;

    const int DSMEM = STAGES * STAGE_BYTES;
    cudaFuncSetAttribute(gemm_mma<0, false>, cudaFuncAttributeMaxDynamicSharedMemorySize, DSMEM);
    cudaFuncSetAttribute(gemm_mma<1, true>,  cudaFuncAttributeMaxDynamicSharedMemorySize, DSMEM);
    cudaFuncSetAttribute(gemm_mma<2, false>, cudaFuncAttributeMaxDynamicSharedMemorySize, DSMEM);

    // input splits + weight converts
    {
        int n4 = M * C / 4;
        split_kernel<<<(n4 + 255) / 256, 256>>>(x, xhi, xlo, n4);
        split_kernel<<<(n4 + 255) / 256, 256>>>(src, shi, slo, n4);
        int w4 = C * C / 4;
        wconv_kernel<<<(w4 + 255) / 256, 256>>>(Wq, wq, w4);
        wconv_kernel<<<(w4 + 255) / 256, 256>>>(Wk, wk, w4);
        wconv_kernel<<<(w4 + 255) / 256, 256>>>(Wv, wv, w4);
        wconv_kernel<<<(w4 + 255) / 256, 256>>>(Wm, wm, w4);
        int w14 = 4 * C * C / 4;
        wconv_kernel<<<(w14 + 255) / 256, 256>>>(W1, w1, w14);
        int w24 = 2 * C * C / 4;
        wconv_kernel<<<(w24 + 255) / 256, 256>>>(W2, w2, w24);
    }

    dim3 gq(C / 128, M / 128);
    // q, k projections with fused elu+1 + RoPE; v plain fp32
    gemm_mma<2, false><<<gq, 256, DSMEM>>>(xhi, xlo, C, xhi, xlo, C, C,
                                           wq, q, nullptr, nullptr, M, C, C);
    gemm_mma<2, false><<<gq, 256, DSMEM>>>(shi, slo, C, shi, slo, C, C,
                                           wk, k, nullptr, nullptr, M, C, C);
    gemm_mma<0, false><<<gq, 256, DSMEM>>>(shi, slo, C, shi, slo, C, C,
                                           wv, v, nullptr, nullptr, M, C, C);

    // KV / Ksum
    kv_reduce<<<dim3(NCHUNK, NH), 256>>>(k, v, kvp, ksp, NH);
    {
        int tot = NH * 1024 + NH * 32;
        kv_finalize<<<(tot + 255) / 256, 256>>>(kvp, ksp, kv, ksum, NH);
    }

    // attention out -> msg hi/lo
    attn_out<<<M, 256>>>(q, kv, ksum, mhi, mlo);

    // t1 = LN1(msg @ Wm^T) -> hi/lo
    gemm_mma<0, false><<<gq, 256, DSMEM>>>(mhi, mlo, C, mhi, mlo, C, C,
                                           wm, t1f, nullptr, nullptr, M, C, C);
    ln_kernel<true><<<M, 256>>>(t1f, ln1g, ln1b, nullptr, nullptr, t1hi, t1lo);

    // h1 = relu([x, t1] @ W1^T) -> hi/lo   (N=512, K=512, Ksplit=256)
    gemm_mma<1, true><<<dim3(4, M / 128), 256, DSMEM>>>(
        xhi, xlo, C, t1hi, t1lo, C, C,
        w1, nullptr, h1hi, h1lo, M, 2 * C, 2 * C);

    // t2 = h1 @ W2^T (reuse q buffer)
    gemm_mma<0, false><<<gq, 256, DSMEM>>>(h1hi, h1lo, 2 * C, h1hi, h1lo, 2 * C, 2 * C,
                                           w2, q, nullptr, nullptr, M, C, 2 * C);

    // out = x + LN2(t2)
    ln_kernel<false><<<M, 256>>>(q, ln2g, ln2b, x, outp, nullptr, nullptr);
}

// round 6
// speedup vs baseline: 3.5885x; 1.3552x over previous
#include <cuda_runtime.h>
#include <cuda_fp16.h>
#include <cstdint>
#include <math.h>

// ---------------------------------------------------------------------------
// RoPE-LoFTR encoder layer. GEMMs via mma.sync fp16 (single-term fp16 both
// operands, fp32 accum), ldmatrix loads, 4-stage cp.async ring, RoPE fused.
// N=4, L=16384 (128x128), C=256, NHEAD=8, D=32.
// ---------------------------------------------------------------------------

#define MAXM   65536
#define CDIM   256
#define LSEQ   16384
#define NHEADS 8
#define NCHUNK 32

typedef __half hf;

// fp32 buffers
__device__ float g_q  [(size_t)MAXM * CDIM];
__device__ float g_k  [(size_t)MAXM * CDIM];
__device__ float g_v  [(size_t)MAXM * CDIM];
__device__ float g_t1f[(size_t)MAXM * CDIM];
__device__ float g_kvp[(size_t)NCHUNK * 32 * 32 * 32];
__device__ float g_ksp[(size_t)NCHUNK * 32 * 32];
__device__ float g_kv [(size_t)32 * 32 * 32];
__device__ float g_ksum[(size_t)32 * 32];

// fp16 activation buffers
__device__ hf g_xh [(size_t)MAXM * CDIM];
__device__ hf g_sh [(size_t)MAXM * CDIM];
__device__ hf g_mh [(size_t)MAXM * CDIM];
__device__ hf g_t1h[(size_t)MAXM * CDIM];
__device__ hf g_h1h[(size_t)MAXM * 2 * CDIM];
// fp16 weights
__device__ hf g_wq[CDIM * CDIM];
__device__ hf g_wk[CDIM * CDIM];
__device__ hf g_wv[CDIM * CDIM];
__device__ hf g_wm[CDIM * CDIM];
__device__ hf g_w1[2 * CDIM * 2 * CDIM];
__device__ hf g_w2[CDIM * 2 * CDIM];

// ---------------------------------------------------------------------------
#define CP_ASYNC16(dst, src) \
    asm volatile("cp.async.cg.shared.global [%0], [%1], 16;" \
                 :: "r"(dst), "l"(src) : "memory")
#define CP_COMMIT() asm volatile("cp.async.commit_group;" ::: "memory")
#define CP_WAIT(n)  asm volatile("cp.async.wait_group %0;" :: "n"(n) : "memory")

#define LDMATRIX_X4(r0, r1, r2, r3, addr) \
    asm volatile("ldmatrix.sync.aligned.m8n8.x4.shared.b16 {%0,%1,%2,%3}, [%4];" \
                 : "=r"(r0), "=r"(r1), "=r"(r2), "=r"(r3) : "r"(addr))

__device__ __forceinline__ uint32_t smem_u32(const void* p) {
    uint32_t a;
    asm("{ .reg .u64 t; cvta.to.shared.u64 t, %1; cvt.u32.u64 %0, t; }"
        : "=r"(a) : "l"(p));
    return a;
}

__device__ __forceinline__ void mma16816(float* c, const uint32_t* a,
                                         const uint32_t* b) {
    asm volatile(
        "mma.sync.aligned.m16n8k16.row.col.f32.f16.f16.f32 "
        "{%0,%1,%2,%3}, {%4,%5,%6,%7}, {%8,%9}, {%0,%1,%2,%3};"
        : "+f"(c[0]), "+f"(c[1]), "+f"(c[2]), "+f"(c[3])
        : "r"(a[0]), "r"(a[1]), "r"(a[2]), "r"(a[3]), "r"(b[0]), "r"(b[1]));
}

// smem tile: 128 rows x 32 fp16 (64B/row); 16B chunk swizzle: ch ^= (row>>1)&3
__device__ __forceinline__ uint32_t tile_off(int row, int ch) {
    return (uint32_t)(row * 64 + ((ch ^ ((row >> 1) & 3)) << 4));
}

__device__ __forceinline__ uint32_t pack_h2(float f0, float f1) {
    hf h0 = __float2half_rn(f0);
    hf h1 = __float2half_rn(f1);
    return (uint32_t)__half_as_ushort(h1) << 16 |
           (uint32_t)__half_as_ushort(h0);
}

// ---------------------------------------------------------------------------
// GEMM: C[M,N] = A[M,K] @ B[N,K]^T; A,B fp16, fp32 accum.
// A switches to A2 at k=Ksplit (concat GEMM).
// Tile 128x128, BK=32, 256 threads (8 warps, 4m x 2n), 4-stage cp.async ring.
// OMODE 0: fp32 out. OMODE 1: fp16 out (after optional RELU).
// OMODE 2: elu+1 then RoPE, fp32 out (for q/k; requires N==256).
// ---------------------------------------------------------------------------
#define STAGES 4
#define STAGE_BYTES 16384

template <int OMODE, bool RELU>
__global__ __launch_bounds__(256) void gemm_mma(
    const hf* __restrict__ A, int lda,
    const hf* __restrict__ A2, int lda2, int Ksplit,
    const hf* __restrict__ B,
    float* __restrict__ Cf, hf* __restrict__ Ch,
    int M, int N, int K)
{
    extern __shared__ char smem[];

    const int tid  = threadIdx.x;
    const int lane = tid & 31;
    const int wid  = tid >> 5;
    const int g    = lane >> 2;
    const int tig  = lane & 3;
    const int wm   = wid & 3;
    const int wn   = wid >> 2;
    const int bm   = blockIdx.y * 128;
    const int bn   = blockIdx.x * 128;
    const int nkc  = K / 32;

    const int a_lrow  = lane & 15;
    const int a_khalf = lane >> 4;
    const int b_lrow  = lane & 7;
    const int b_kpart = (lane >> 3) & 1;
    const int b_npart = lane >> 4;

    float acc[2][8][4];
#pragma unroll
    for (int i = 0; i < 2; i++)
#pragma unroll
        for (int j = 0; j < 8; j++)
#pragma unroll
            for (int e = 0; e < 4; e++) acc[i][j][e] = 0.f;

    const int slot0 = tid, slot1 = tid + 256;

    auto issue = [&](int kc) {
        const int stg = kc & (STAGES - 1);
        const int kin = kc * 32;
        const hf* Asrc; int ald, koff;
        if (kin < Ksplit) { Asrc = A;  ald = lda;  koff = kin; }
        else              { Asrc = A2; ald = lda2; koff = kin - Ksplit; }

        uint32_t sA = smem_u32(smem + stg * STAGE_BYTES);
        uint32_t sB = sA + 8192;
        {
            int row = slot0 >> 2, ch = slot0 & 3;
            CP_ASYNC16(sA + tile_off(row, ch),
                       Asrc + (size_t)(bm + row) * ald + koff + ch * 8);
        }
        {
            int row = slot1 >> 2, ch = slot1 & 3;
            CP_ASYNC16(sA + tile_off(row, ch),
                       Asrc + (size_t)(bm + row) * ald + koff + ch * 8);
        }
        {
            int row = slot0 >> 2, ch = slot0 & 3;
            CP_ASYNC16(sB + tile_off(row, ch),
                       B + (size_t)(bn + row) * K + kin + ch * 8);
        }
        {
            int row = slot1 >> 2, ch = slot1 & 3;
            CP_ASYNC16(sB + tile_off(row, ch),
                       B + (size_t)(bn + row) * K + kin + ch * 8);
        }
        CP_COMMIT();
    };

    issue(0); issue(1); issue(2);

    for (int kc = 0; kc < nkc; kc++) {
        CP_WAIT(2);
        __syncthreads();
        if (kc + 3 < nkc) issue(kc + 3);
        else CP_COMMIT();                 // keep group count consistent

        const uint32_t sA = smem_u32(smem + (kc & (STAGES - 1)) * STAGE_BYTES);
        const uint32_t sB = sA + 8192;

#pragma unroll
        for (int s = 0; s < 2; s++) {
            uint32_t af[2][4];
#pragma unroll
            for (int mi = 0; mi < 2; mi++) {
                int r  = wm * 32 + mi * 16 + a_lrow;
                int ch = 2 * s + a_khalf;
                LDMATRIX_X4(af[mi][0], af[mi][1], af[mi][2], af[mi][3],
                            sA + tile_off(r, ch));
            }
            uint32_t bfr[8][2];
#pragma unroll
            for (int njp = 0; njp < 4; njp++) {
                int r  = wn * 64 + (2 * njp + b_npart) * 8 + b_lrow;
                int ch = 2 * s + b_kpart;
                LDMATRIX_X4(bfr[2 * njp][0], bfr[2 * njp][1],
                            bfr[2 * njp + 1][0], bfr[2 * njp + 1][1],
                            sB + tile_off(r, ch));
            }
#pragma unroll
            for (int mi = 0; mi < 2; mi++)
#pragma unroll
                for (int nj = 0; nj < 8; nj++)
                    mma16816(acc[mi][nj], af[mi], bfr[nj]);
        }
    }

    // epilogue
#pragma unroll
    for (int mi = 0; mi < 2; mi++) {
        int rbase = bm + wm * 32 + mi * 16 + g;
#pragma unroll
        for (int nj = 0; nj < 8; nj++) {
            int col = bn + wn * 64 + nj * 8 + 2 * tig;
            float c0 = acc[mi][nj][0], c1 = acc[mi][nj][1];
            float c2 = acc[mi][nj][2], c3 = acc[mi][nj][3];
            if (OMODE == 2) {
                // elu+1 then RoPE; col is even, (col, col+1) is a rotate pair
                int rem = col >> 1;            // 0..127 (N == 256)
                int tt  = rem & 15;
                int qf  = tt >> 1;
                float dv = expf(-(float)qf * 1.1512925465f);
                bool odd = (tt & 1) != 0;
#pragma unroll
                for (int rr = 0; rr < 2; rr++) {
                    int r = rbase + rr * 8;
                    int l = r & (LSEQ - 1);
                    int ii = l >> 7, jj = l & 127;
                    float pos = odd ? (float)(jj + 1) : (float)(ii + 1);
                    float sn, cs;
                    sincosf(pos * dv, &sn, &cs);
                    float u0 = rr ? c2 : c0;
                    float u1 = rr ? c3 : c1;
                    float x0 = u0 > 0.f ? u0 + 1.f : expf(u0);
                    float x1 = u1 > 0.f ? u1 + 1.f : expf(u1);
                    float2 o;
                    o.x = x0 * cs - x1 * sn;
                    o.y = x1 * cs + x0 * sn;
                    *(float2*)(Cf + (size_t)r * N + col) = o;
                }
            } else {
                if (RELU) {
                    c0 = fmaxf(c0, 0.f); c1 = fmaxf(c1, 0.f);
                    c2 = fmaxf(c2, 0.f); c3 = fmaxf(c3, 0.f);
                }
                if (OMODE == 0) {
                    *(float2*)(Cf + (size_t)rbase * N + col)       = make_float2(c0, c1);
                    *(float2*)(Cf + (size_t)(rbase + 8) * N + col) = make_float2(c2, c3);
                } else {
                    *(uint32_t*)(Ch + (size_t)rbase * N + col)       = pack_h2(c0, c1);
                    *(uint32_t*)(Ch + (size_t)(rbase + 8) * N + col) = pack_h2(c2, c3);
                }
            }
        }
    }
}

// ---------------------------------------------------------------------------
// fp32 -> fp16 convert
// ---------------------------------------------------------------------------
__global__ __launch_bounds__(256) void hconv_kernel(const float* __restrict__ in,
                                                    hf* __restrict__ out, int n4)
{
    int i = blockIdx.x * 256 + threadIdx.x;
    if (i >= n4) return;
    float4 f = ((const float4*)in)[i];
    uint2 o;
    o.x = pack_h2(f.x, f.y);
    o.y = pack_h2(f.z, f.w);
    ((uint2*)out)[i] = o;
}

// ---------------------------------------------------------------------------
// KV / Ksum chunked reduction (deterministic), then finalize
// ---------------------------------------------------------------------------
__global__ __launch_bounds__(256) void kv_reduce(
    const float* __restrict__ Kr, const float* __restrict__ V,
    float* __restrict__ kvp, float* __restrict__ ksp, int NH)
{
    int chunk = blockIdx.x, nh = blockIdx.y;
    int n = nh >> 3, h = nh & 7;
    int t = threadIdx.x, d = t & 31, eg = t >> 5;
    const int rows = LSEQ / NCHUNK;
    int s0 = chunk * rows;
    __shared__ float Ks[8][32], Vs[8][32];
    float a0 = 0.f, a1 = 0.f, a2 = 0.f, a3 = 0.f, ks = 0.f;
    int ls = t >> 5, ld = t & 31;
    for (int s = 0; s < rows; s += 8) {
        size_t off = (size_t)(n * LSEQ + s0 + s + ls) * CDIM + h * 32 + ld;
        Ks[ls][ld] = Kr[off];
        Vs[ls][ld] = V[off];
        __syncthreads();
#pragma unroll
        for (int ss = 0; ss < 8; ss++) {
            float kd = Ks[ss][d];
            if (eg == 0) ks += kd;
            const float* vr = &Vs[ss][eg * 4];
            a0 += kd * vr[0]; a1 += kd * vr[1];
            a2 += kd * vr[2]; a3 += kd * vr[3];
        }
        __syncthreads();
    }
    size_t pbase = ((size_t)(chunk * NH + nh) * 32 + d) * 32 + eg * 4;
    kvp[pbase + 0] = a0; kvp[pbase + 1] = a1;
    kvp[pbase + 2] = a2; kvp[pbase + 3] = a3;
    if (eg == 0) ksp[(size_t)(chunk * NH + nh) * 32 + d] = ks;
}

__global__ void kv_finalize(const float* __restrict__ kvp, const float* __restrict__ ksp,
                            float* __restrict__ kv, float* __restrict__ ksum, int NH)
{
    int i = blockIdx.x * blockDim.x + threadIdx.x;
    int tot_kv = NH * 1024, tot_ks = NH * 32;
    if (i < tot_kv) {
        float s = 0.f;
        for (int c = 0; c < NCHUNK; c++) s += kvp[(size_t)c * tot_kv + i];
        kv[i] = s;
    } else if (i < tot_kv + tot_ks) {
        int j = i - tot_kv;
        float s = 0.f;
        for (int c = 0; c < NCHUNK; c++) s += ksp[(size_t)c * tot_ks + j];
        ksum[j] = s;
    }
}

// ---------------------------------------------------------------------------
// attention output per (token, head); writes msg as fp16
// ---------------------------------------------------------------------------
__global__ __launch_bounds__(256) void attn_out(
    const float* __restrict__ Q, const float* __restrict__ KV,
    const float* __restrict__ Ksum, hf* __restrict__ mh)
{
    int m = blockIdx.x, w = threadIdx.x >> 5, lane = threadIdx.x & 31;
    int n = m / LSEQ, nh = n * NHEADS + w;
    float qv = Q[(size_t)m * CDIM + w * 32 + lane];
    float z = qv * Ksum[nh * 32 + lane];
#pragma unroll
    for (int o = 16; o; o >>= 1) z += __shfl_xor_sync(0xffffffffu, z, o);
    float Z = 1.f / (z + 1e-6f);
    const float* kvh = KV + (size_t)nh * 1024;
    float acc = 0.f;
#pragma unroll
    for (int d = 0; d < 32; d++)
        acc += __shfl_sync(0xffffffffu, qv, d) * kvh[d * 32 + lane];
    mh[(size_t)m * CDIM + w * 32 + lane] = __float2half_rn(acc * Z);
}

// ---------------------------------------------------------------------------
// LayerNorm over C=256. HOUT: write fp16. Else fp32 (+optional residual).
// ---------------------------------------------------------------------------
template <bool HOUT>
__global__ __launch_bounds__(256) void ln_kernel(
    const float* __restrict__ in, const float* __restrict__ g,
    const float* __restrict__ b, const float* __restrict__ resid,
    float* __restrict__ outf, hf* __restrict__ oh)
{
    int row = blockIdx.x, t = threadIdx.x;
    int lane = t & 31, w = t >> 5;
    size_t base = (size_t)row * CDIM + t;
    float x = in[base];
    __shared__ float red[8];
    __shared__ float stat;
    float s = x;
#pragma unroll
    for (int o = 16; o; o >>= 1) s += __shfl_xor_sync(0xffffffffu, s, o);
    if (lane == 0) red[w] = s;
    __syncthreads();
    if (t == 0) {
        float m = 0.f;
#pragma unroll
        for (int i = 0; i < 8; i++) m += red[i];
        stat = m * (1.f / 256.f);
    }
    __syncthreads();
    float d = x - stat;
    __syncthreads();
    float vs = d * d;
#pragma unroll
    for (int o = 16; o; o >>= 1) vs += __shfl_xor_sync(0xffffffffu, vs, o);
    if (lane == 0) red[w] = vs;
    __syncthreads();
    if (t == 0) {
        float vv = 0.f;
#pragma unroll
        for (int i = 0; i < 8; i++) vv += red[i];
        stat = rsqrtf(vv * (1.f / 256.f) + 1e-5f);
    }
    __syncthreads();
    float r = d * stat * g[t] + b[t];
    if (HOUT) {
        oh[base] = __float2half_rn(r);
    } else {
        if (resid) r += resid[base];
        outf[base] = r;
    }
}

// ---------------------------------------------------------------------------
extern "C" void kernel_launch(void* const* d_in, const int* in_sizes, int n_in,
                              void* d_out, int out_size)
{
    const float* x    = (const float*)d_in[0];
    const float* src  = (const float*)d_in[1];
    const float* Wq   = (const float*)d_in[2];
    const float* Wk   = (const float*)d_in[3];
    const float* Wv   = (const float*)d_in[4];
    const float* Wm   = (const float*)d_in[5];
    const float* W1   = (const float*)d_in[6];
    const float* W2   = (const float*)d_in[7];
    const float* ln1g = (const float*)d_in[8];
    const float* ln1b = (const float*)d_in[9];
    const float* ln2g = (const float*)d_in[10];
    const float* ln2b = (const float*)d_in[11];

    const int C = CDIM;
    const int M = in_sizes[0] / C;
    const int Nb = M / LSEQ;
    const int NH = Nb * NHEADS;

    float *q, *k, *v, *t1f, *kvp, *ksp, *kv, *ksum;
    cudaGetSymbolAddress((void**)&q, g_q);
    cudaGetSymbolAddress((void**)&k, g_k);
    cudaGetSymbolAddress((void**)&v, g_v);
    cudaGetSymbolAddress((void**)&t1f, g_t1f);
    cudaGetSymbolAddress((void**)&kvp, g_kvp);
    cudaGetSymbolAddress((void**)&ksp, g_ksp);
    cudaGetSymbolAddress((void**)&kv, g_kv);
    cudaGetSymbolAddress((void**)&ksum, g_ksum);

    hf *xh, *sh, *mh, *t1h, *h1h;
    hf *wq, *wk, *wv, *wm, *w1, *w2;
    cudaGetSymbolAddress((void**)&xh, g_xh);
    cudaGetSymbolAddress((void**)&sh, g_sh);
    cudaGetSymbolAddress((void**)&mh, g_mh);
    cudaGetSymbolAddress((void**)&t1h, g_t1h);
    cudaGetSymbolAddress((void**)&h1h, g_h1h);
    cudaGetSymbolAddress((void**)&wq, g_wq);
    cudaGetSymbolAddress((void**)&wk, g_wk);
    cudaGetSymbolAddress((void**)&wv, g_wv);
    cudaGetSymbolAddress((void**)&wm, g_wm);
    cudaGetSymbolAddress((void**)&w1, g_w1);
    cudaGetSymbolAddress((void**)&w2, g_w2);

    float* outp = (float*)d_out;

    const int DSMEM = STAGES * STAGE_BYTES;
    cudaFuncSetAttribute(gemm_mma<0, false>, cudaFuncAttributeMaxDynamicSharedMemorySize, DSMEM);
    cudaFuncSetAttribute(gemm_mma<1, true>,  cudaFuncAttributeMaxDynamicSharedMemorySize, DSMEM);
    cudaFuncSetAttribute(gemm_mma<2, false>, cudaFuncAttributeMaxDynamicSharedMemorySize, DSMEM);

    // input + weight converts
    {
        int n4 = M * C / 4;
        hconv_kernel<<<(n4 + 255) / 256, 256>>>(x, xh, n4);
        hconv_kernel<<<(n4 + 255) / 256, 256>>>(src, sh, n4);
        int w4 = C * C / 4;
        hconv_kernel<<<(w4 + 255) / 256, 256>>>(Wq, wq, w4);
        hconv_kernel<<<(w4 + 255) / 256, 256>>>(Wk, wk, w4);
        hconv_kernel<<<(w4 + 255) / 256, 256>>>(Wv, wv, w4);
        hconv_kernel<<<(w4 + 255) / 256, 256>>>(Wm, wm, w4);
        int w14 = 4 * C * C / 4;
        hconv_kernel<<<(w14 + 255) / 256, 256>>>(W1, w1, w14);
        int w24 = 2 * C * C / 4;
        hconv_kernel<<<(w24 + 255) / 256, 256>>>(W2, w2, w24);
    }

    dim3 gq(C / 128, M / 128);
    // q, k projections with fused elu+1 + RoPE; v plain fp32
    gemm_mma<2, false><<<gq, 256, DSMEM>>>(xh, C, xh, C, C,
                                           wq, q, nullptr, M, C, C);
    gemm_mma<2, false><<<gq, 256, DSMEM>>>(sh, C, sh, C, C,
                                           wk, k, nullptr, M, C, C);
    gemm_mma<0, false><<<gq, 256, DSMEM>>>(sh, C, sh, C, C,
                                           wv, v, nullptr, M, C, C);

    // KV / Ksum
    kv_reduce<<<dim3(NCHUNK, NH), 256>>>(k, v, kvp, ksp, NH);
    {
        int tot = NH * 1024 + NH * 32;
        kv_finalize<<<(tot + 255) / 256, 256>>>(kvp, ksp, kv, ksum, NH);
    }

    // attention out -> msg fp16
    attn_out<<<M, 256>>>(q, kv, ksum, mh);

    // t1 = LN1(msg @ Wm^T) -> fp16
    gemm_mma<0, false><<<gq, 256, DSMEM>>>(mh, C, mh, C, C,
                                           wm, t1f, nullptr, M, C, C);
    ln_kernel<true><<<M, 256>>>(t1f, ln1g, ln1b, nullptr, nullptr, t1h);

    // h1 = relu([x, t1] @ W1^T) -> fp16   (N=512, K=512, Ksplit=256)
    gemm_mma<1, true><<<dim3(4, M / 128), 256, DSMEM>>>(
        xh, C, t1h, C, C, w1, nullptr, h1h, M, 2 * C, 2 * C);

    // t2 = h1 @ W2^T (reuse q buffer)
    gemm_mma<0, false><<<gq, 256, DSMEM>>>(h1h, 2 * C, h1h, 2 * C, 2 * C,
                                           w2, q, nullptr, M, C, 2 * C);

    // out = x + LN2(t2)
    ln_kernel<false><<<M, 256>>>(q, ln2g, ln2b, x, outp, nullptr);
}